// round 1
// baseline (speedup 1.0000x reference)
#include <cuda_runtime.h>
#include <cstdint>

#define BB   4
#define TT   2048
#define DDIM 512
#define HH   8
#define DHH  64
#define BT   8192        // BB*TT
#define FFD  2048        // 4*DDIM
#define QKVN 1536        // 3*DDIM

// ---------------- scratch (no allocations allowed) ----------------
__device__ float g_h   [(size_t)BT * DDIM];   // LN output (reused for both LNs)
__device__ float g_qkv [(size_t)BT * QKVN];   // fused q|k|v per token
__device__ float g_o   [(size_t)BT * DDIM];   // attention output (heads concat)
__device__ float g_x1  [(size_t)BT * DDIM];   // x + attn_proj
__device__ float g_ff1 [(size_t)BT * FFD];    // relu(h2@W1+b1)
__device__ float g_wqkv[(size_t)DDIM * QKVN]; // repacked [D][3*D] row-major

// ---------------- weight repack: (H,D,DH)x3 -> [D][1536] ----------------
__global__ void repack_qkv_kernel(const float* __restrict__ Wq,
                                  const float* __restrict__ Wk,
                                  const float* __restrict__ Wv) {
    int idx = blockIdx.x * blockDim.x + threadIdx.x;
    if (idx >= HH * DDIM * DHH) return;
    int h = idx / (DDIM * DHH);
    int r = idx % (DDIM * DHH);
    int d = r / DHH;
    int e = r % DHH;
    int col = h * DHH + e;
    g_wqkv[(size_t)d * QKVN + col]             = Wq[idx];
    g_wqkv[(size_t)d * QKVN + DDIM + col]      = Wk[idx];
    g_wqkv[(size_t)d * QKVN + 2 * DDIM + col]  = Wv[idx];
}

// ---------------- LayerNorm: one block (128 thr) per row of 512 ----------------
__global__ __launch_bounds__(128) void ln_kernel(const float* __restrict__ x,
                                                 const float* __restrict__ g,
                                                 const float* __restrict__ b,
                                                 float* __restrict__ out) {
    int row = blockIdx.x;
    int t = threadIdx.x;                        // 0..127, each owns one float4
    const float4* xr = (const float4*)(x + (size_t)row * DDIM);
    float4 v = xr[t];
    float s = v.x + v.y + v.z + v.w;
    float q = v.x * v.x + v.y * v.y + v.z * v.z + v.w * v.w;
    #pragma unroll
    for (int off = 16; off; off >>= 1) {
        s += __shfl_xor_sync(0xffffffffu, s, off);
        q += __shfl_xor_sync(0xffffffffu, q, off);
    }
    __shared__ float ss[4], qs[4];
    if ((t & 31) == 0) { ss[t >> 5] = s; qs[t >> 5] = q; }
    __syncthreads();
    s = ss[0] + ss[1] + ss[2] + ss[3];
    q = qs[0] + qs[1] + qs[2] + qs[3];
    float mean = s * (1.0f / DDIM);
    float var  = q * (1.0f / DDIM) - mean * mean;
    float inv  = rsqrtf(var + 1e-5f);
    float4 gv = ((const float4*)g)[t];
    float4 bv = ((const float4*)b)[t];
    float4 ov;
    ov.x = (v.x - mean) * inv * gv.x + bv.x;
    ov.y = (v.y - mean) * inv * gv.y + bv.y;
    ov.z = (v.z - mean) * inv * gv.z + bv.z;
    ov.w = (v.w - mean) * inv * gv.w + bv.w;
    ((float4*)(out + (size_t)row * DDIM))[t] = ov;
}

// ---------------- generic SGEMM: C[M,N] = A[M,K] @ B[K,N] (+bias)(+relu)(+res) ----------------
// 64x64 tile, BK=16, 256 threads, 4x4 per thread.
__global__ __launch_bounds__(256) void gemm_kernel(const float* __restrict__ A,
                                                   const float* __restrict__ Bm,
                                                   const float* __restrict__ bias,
                                                   const float* __restrict__ res,
                                                   float* __restrict__ C,
                                                   int M, int N, int K, int relu) {
    __shared__ float As[16][68];   // [k][m], padded
    __shared__ float Bs[16][64];   // [k][n]
    const int tid = threadIdx.x;
    const int tx = tid & 15, ty = tid >> 4;
    const int brow = blockIdx.y * 64, bcol = blockIdx.x * 64;

    const int arow = tid >> 2;            // 0..63
    const int ak   = (tid & 3) * 4;       // 0,4,8,12
    const int bk   = tid >> 4;            // 0..15
    const int bn   = (tid & 15) * 4;      // 0..60

    const float* Aptr = A  + (size_t)(brow + arow) * K + ak;
    const float* Bptr = Bm + (size_t)bk * N + bcol + bn;

    float acc[4][4];
    #pragma unroll
    for (int i = 0; i < 4; i++)
        #pragma unroll
        for (int j = 0; j < 4; j++) acc[i][j] = 0.0f;

    for (int k0 = 0; k0 < K; k0 += 16) {
        float4 a4 = *(const float4*)(Aptr + k0);
        float4 b4 = *(const float4*)(Bptr + (size_t)k0 * N);
        As[ak + 0][arow] = a4.x;
        As[ak + 1][arow] = a4.y;
        As[ak + 2][arow] = a4.z;
        As[ak + 3][arow] = a4.w;
        *(float4*)&Bs[bk][bn] = b4;
        __syncthreads();
        #pragma unroll
        for (int k = 0; k < 16; k++) {
            float4 a = *(const float4*)&As[k][ty * 4];
            float4 bq = *(const float4*)&Bs[k][tx * 4];
            float av[4] = {a.x, a.y, a.z, a.w};
            float bvv[4] = {bq.x, bq.y, bq.z, bq.w};
            #pragma unroll
            for (int i = 0; i < 4; i++)
                #pragma unroll
                for (int j = 0; j < 4; j++)
                    acc[i][j] += av[i] * bvv[j];
        }
        __syncthreads();
    }

    #pragma unroll
    for (int i = 0; i < 4; i++) {
        int r = brow + ty * 4 + i;
        #pragma unroll
        for (int j = 0; j < 4; j++) {
            int c = bcol + tx * 4 + j;
            float v = acc[i][j];
            if (bias) v += bias[c];
            if (relu) v = fmaxf(v, 0.0f);
            if (res)  v += res[(size_t)r * N + c];
            C[(size_t)r * N + c] = v;
        }
    }
}

// ---------------- flash attention: 64q x 64k tiles, DH=64, causal ----------------
#define NEG_BIG (-1e30f)
#define ATTN_SMEM (3 * 64 * 65 * 4)

__global__ __launch_bounds__(256) void attn_kernel(const float* __restrict__ qkv,
                                                   float* __restrict__ o_out) {
    extern __shared__ float sm[];
    float (*Qs)[65] = (float(*)[65])sm;                 // Q tile  [q][e]
    float (*Ps)[65] = (float(*)[65])(sm + 64 * 65);     // K tile [k][e], reused as P [q][k]
    float (*Vs)[65] = (float(*)[65])(sm + 2 * 64 * 65); // V tile [k][e]

    const int it = blockIdx.x;    // query tile (0..31)
    const int h  = blockIdx.y;
    const int b  = blockIdx.z;
    const int qbase = it * 64;
    const int tid = threadIdx.x;
    const int tx = tid & 15, ty = tid >> 4;
    const float scale = 0.044194173824159216f;  // 512^-0.5 (source scales by D, not DH)

    // load Q tile (once)
    {
        int r  = tid >> 2;
        int c0 = (tid & 3) * 16;
        const float* src = qkv + (size_t)(b * TT + qbase + r) * QKVN + h * DHH + c0;
        #pragma unroll
        for (int u = 0; u < 16; u += 4) {
            float4 v = *(const float4*)(src + u);
            Qs[r][c0 + u + 0] = v.x; Qs[r][c0 + u + 1] = v.y;
            Qs[r][c0 + u + 2] = v.z; Qs[r][c0 + u + 3] = v.w;
        }
    }

    float oacc[4][4];
    float m[4], l[4];
    #pragma unroll
    for (int i = 0; i < 4; i++) {
        m[i] = NEG_BIG; l[i] = 0.0f;
        #pragma unroll
        for (int j = 0; j < 4; j++) oacc[i][j] = 0.0f;
    }

    for (int jt = 0; jt <= it; jt++) {
        const int kbase = jt * 64;
        // load K -> Ps, V -> Vs
        {
            int r  = tid >> 2;
            int c0 = (tid & 3) * 16;
            const float* ksrc = qkv + (size_t)(b * TT + kbase + r) * QKVN + DDIM + h * DHH + c0;
            const float* vsrc = ksrc + DDIM;
            #pragma unroll
            for (int u = 0; u < 16; u += 4) {
                float4 kv = *(const float4*)(ksrc + u);
                float4 vv = *(const float4*)(vsrc + u);
                Ps[r][c0 + u + 0] = kv.x; Ps[r][c0 + u + 1] = kv.y;
                Ps[r][c0 + u + 2] = kv.z; Ps[r][c0 + u + 3] = kv.w;
                Vs[r][c0 + u + 0] = vv.x; Vs[r][c0 + u + 1] = vv.y;
                Vs[r][c0 + u + 2] = vv.z; Vs[r][c0 + u + 3] = vv.w;
            }
        }
        __syncthreads();

        // S = Q @ K^T (64x64, thread owns 4x4)
        float s[4][4];
        #pragma unroll
        for (int i = 0; i < 4; i++)
            #pragma unroll
            for (int j = 0; j < 4; j++) s[i][j] = 0.0f;
        #pragma unroll 4
        for (int e = 0; e < 64; e++) {
            float qv[4], kv[4];
            #pragma unroll
            for (int i = 0; i < 4; i++) qv[i] = Qs[ty * 4 + i][e];
            #pragma unroll
            for (int j = 0; j < 4; j++) kv[j] = Ps[tx * 4 + j][e];
            #pragma unroll
            for (int i = 0; i < 4; i++)
                #pragma unroll
                for (int j = 0; j < 4; j++)
                    s[i][j] += qv[i] * kv[j];
        }
        __syncthreads();   // all reads of K (in Ps) done before P overwrites it

        const bool diag = (jt == it);
        #pragma unroll
        for (int i = 0; i < 4; i++) {
            int rloc = ty * 4 + i;
            float mt = NEG_BIG;
            #pragma unroll
            for (int j = 0; j < 4; j++) {
                float v = s[i][j] * scale;
                if (diag && (tx * 4 + j > rloc)) v = NEG_BIG;
                s[i][j] = v;
                mt = fmaxf(mt, v);
            }
            #pragma unroll
            for (int off = 1; off < 16; off <<= 1)
                mt = fmaxf(mt, __shfl_xor_sync(0xffffffffu, mt, off));
            float newm = fmaxf(m[i], mt);
            float alpha = __expf(m[i] - newm);   // 0 on first tile (m = -1e30)
            float rs = 0.0f;
            #pragma unroll
            for (int j = 0; j < 4; j++) {
                float p = __expf(s[i][j] - newm); // masked -> underflow -> 0
                s[i][j] = p;
                rs += p;
            }
            #pragma unroll
            for (int off = 1; off < 16; off <<= 1)
                rs += __shfl_xor_sync(0xffffffffu, rs, off);
            l[i] = l[i] * alpha + rs;
            m[i] = newm;
            #pragma unroll
            for (int j = 0; j < 4; j++) oacc[i][j] *= alpha;
        }

        // store P into Ps [q][k]
        #pragma unroll
        for (int i = 0; i < 4; i++)
            #pragma unroll
            for (int j = 0; j < 4; j++)
                Ps[ty * 4 + i][tx * 4 + j] = s[i][j];
        __syncthreads();

        // O += P @ V
        #pragma unroll 4
        for (int c = 0; c < 64; c++) {
            float pv[4], vv[4];
            #pragma unroll
            for (int i = 0; i < 4; i++) pv[i] = Ps[ty * 4 + i][c];
            #pragma unroll
            for (int j = 0; j < 4; j++) vv[j] = Vs[c][tx * 4 + j];
            #pragma unroll
            for (int i = 0; i < 4; i++)
                #pragma unroll
                for (int j = 0; j < 4; j++)
                    oacc[i][j] += pv[i] * vv[j];
        }
        __syncthreads();   // protect Ps/Vs before next tile's load
    }

    // write O / l  -> g_o[(b,t),(h,e)]
    #pragma unroll
    for (int i = 0; i < 4; i++) {
        float invl = 1.0f / l[i];
        int gr = b * TT + qbase + ty * 4 + i;
        float4 ov;
        ov.x = oacc[i][0] * invl; ov.y = oacc[i][1] * invl;
        ov.z = oacc[i][2] * invl; ov.w = oacc[i][3] * invl;
        *(float4*)(o_out + (size_t)gr * DDIM + h * DHH + tx * 4) = ov;
    }
}

// ---------------- launch ----------------
extern "C" void kernel_launch(void* const* d_in, const int* in_sizes, int n_in,
                              void* d_out, int out_size) {
    const float* x     = (const float*)d_in[0];
    const float* ln1_g = (const float*)d_in[1];
    const float* ln1_b = (const float*)d_in[2];
    const float* Wq    = (const float*)d_in[3];
    const float* Wk    = (const float*)d_in[4];
    const float* Wv    = (const float*)d_in[5];
    const float* Wproj = (const float*)d_in[6];
    const float* bproj = (const float*)d_in[7];
    const float* W1    = (const float*)d_in[8];
    const float* b1    = (const float*)d_in[9];
    const float* W2    = (const float*)d_in[10];
    const float* b2    = (const float*)d_in[11];
    float* out = (float*)d_out;

    float *p_h, *p_qkv, *p_o, *p_x1, *p_ff1, *p_wqkv;
    cudaGetSymbolAddress((void**)&p_h,    g_h);
    cudaGetSymbolAddress((void**)&p_qkv,  g_qkv);
    cudaGetSymbolAddress((void**)&p_o,    g_o);
    cudaGetSymbolAddress((void**)&p_x1,   g_x1);
    cudaGetSymbolAddress((void**)&p_ff1,  g_ff1);
    cudaGetSymbolAddress((void**)&p_wqkv, g_wqkv);

    cudaFuncSetAttribute(attn_kernel, cudaFuncAttributeMaxDynamicSharedMemorySize, ATTN_SMEM);

    // 1. repack QKV weights
    repack_qkv_kernel<<<(HH * DDIM * DHH + 255) / 256, 256>>>(Wq, Wk, Wv);
    // 2. h = LN(x)
    ln_kernel<<<BT, 128>>>(x, ln1_g, ln1_b, p_h);
    // 3. qkv = h @ Wqkv
    gemm_kernel<<<dim3(QKVN / 64, BT / 64), 256>>>(p_h, p_wqkv, nullptr, nullptr, p_qkv,
                                                   BT, QKVN, DDIM, 0);
    // 4. o = causal_attention(q,k,v)
    attn_kernel<<<dim3(TT / 64, HH, BB), 256, ATTN_SMEM>>>(p_qkv, p_o);
    // 5. x1 = x + o @ Wproj + bproj
    gemm_kernel<<<dim3(DDIM / 64, BT / 64), 256>>>(p_o, Wproj, bproj, x, p_x1,
                                                   BT, DDIM, DDIM, 0);
    // 6. h2 = LN(x1)
    ln_kernel<<<BT, 128>>>(p_x1, ln1_g, ln1_b, p_h);
    // 7. ff1 = relu(h2 @ W1 + b1)
    gemm_kernel<<<dim3(FFD / 64, BT / 64), 256>>>(p_h, W1, b1, nullptr, p_ff1,
                                                  BT, FFD, DDIM, 1);
    // 8. out = x1 + ff1 @ W2 + b2
    gemm_kernel<<<dim3(DDIM / 64, BT / 64), 256>>>(p_ff1, W2, b2, p_x1, out,
                                                   BT, DDIM, FFD, 0);
}

// round 4
// speedup vs baseline: 2.4467x; 2.4467x over previous
#include <cuda_runtime.h>
#include <cuda_bf16.h>
#include <cstdint>

#define BB   4
#define TT   2048
#define DDIM 512
#define HH   8
#define DHH  64
#define BT   8192
#define FFD  2048
#define QKVN 1536

// ---------------- scratch ----------------
__device__ float g_qkv [(size_t)BT * QKVN];
__device__ float g_x1  [(size_t)BT * DDIM];
__device__ float g_wt  [(size_t)FFD * DDIM];             // transposed weight staging (fp32)
__device__ __nv_bfloat16 g_abf [(size_t)BT * 3 * DDIM];  // split activations (A layout)
__device__ __nv_bfloat16 g_abf2[(size_t)BT * 3 * FFD];   // split ff1 (A layout)
__device__ __nv_bfloat16 g_bbf [(size_t)FFD * 3 * DDIM]; // split weights [N,3K] (B layout)

// ---------------- helpers ----------------
__device__ __forceinline__ uint32_t smem_u32(const void* p) {
    uint32_t a;
    asm("{ .reg .u64 t; cvta.to.shared.u64 t, %1; cvt.u32.u64 %0, t; }" : "=r"(a) : "l"(p));
    return a;
}

#define LDSM4(d, addr)                                                                  \
    asm volatile("ldmatrix.sync.aligned.m8n8.x4.shared.b16 {%0,%1,%2,%3}, [%4];"        \
                 : "=r"((d)[0]), "=r"((d)[1]), "=r"((d)[2]), "=r"((d)[3]) : "r"(addr))

__device__ __forceinline__ void mma16816(float* c, const uint32_t* a,
                                         uint32_t b0, uint32_t b1) {
    asm volatile(
        "mma.sync.aligned.m16n8k16.row.col.f32.bf16.bf16.f32 "
        "{%0,%1,%2,%3}, {%4,%5,%6,%7}, {%8,%9}, {%0,%1,%2,%3};"
        : "+f"(c[0]), "+f"(c[1]), "+f"(c[2]), "+f"(c[3])
        : "r"(a[0]), "r"(a[1]), "r"(a[2]), "r"(a[3]), "r"(b0), "r"(b1));
}

__device__ __forceinline__ void split_store4(__nv_bfloat16* base, size_t off, int K,
                                             float a, float b, float c, float d) {
    __nv_bfloat16 h0 = __float2bfloat16(a), h1 = __float2bfloat16(b);
    __nv_bfloat16 h2 = __float2bfloat16(c), h3 = __float2bfloat16(d);
    __nv_bfloat16 l0 = __float2bfloat16(a - __bfloat162float(h0));
    __nv_bfloat16 l1 = __float2bfloat16(b - __bfloat162float(h1));
    __nv_bfloat16 l2 = __float2bfloat16(c - __bfloat162float(h2));
    __nv_bfloat16 l3 = __float2bfloat16(d - __bfloat162float(h3));
    __nv_bfloat162 hA = __halves2bfloat162(h0, h1), hB = __halves2bfloat162(h2, h3);
    __nv_bfloat162 lA = __halves2bfloat162(l0, l1), lB = __halves2bfloat162(l2, l3);
    __nv_bfloat162* p0 = (__nv_bfloat162*)(base + off);
    __nv_bfloat162* p1 = (__nv_bfloat162*)(base + off + K);
    __nv_bfloat162* p2 = (__nv_bfloat162*)(base + off + 2 * (size_t)K);
    p0[0] = hA; p0[1] = hB;     // hi
    p1[0] = hA; p1[1] = hB;     // hi (A layout: hi,hi,lo)
    p2[0] = lA; p2[1] = lB;     // lo
}

__device__ __forceinline__ void split_store2(__nv_bfloat16* base, size_t off, int K,
                                             float a, float b) {
    __nv_bfloat16 h0 = __float2bfloat16(a), h1 = __float2bfloat16(b);
    __nv_bfloat16 l0 = __float2bfloat16(a - __bfloat162float(h0));
    __nv_bfloat16 l1 = __float2bfloat16(b - __bfloat162float(h1));
    __nv_bfloat162 hA = __halves2bfloat162(h0, h1);
    __nv_bfloat162 lA = __halves2bfloat162(l0, l1);
    *(__nv_bfloat162*)(base + off)              = hA;
    *(__nv_bfloat162*)(base + off + K)          = hA;
    *(__nv_bfloat162*)(base + off + 2 * (size_t)K) = lA;
}

// ---------------- prep kernels ----------------
// fp32 [R,K] -> bf16 [R,3K], B-operand layout (hi,lo,hi)
__global__ void splitB_kernel(const float* __restrict__ in, __nv_bfloat16* __restrict__ out,
                              int total, int K) {
    int i = (blockIdx.x * blockDim.x + threadIdx.x) * 4;
    if (i >= total) return;
    int r = i / K, k = i % K;
    float4 v = *(const float4*)(in + i);
    __nv_bfloat16 h0 = __float2bfloat16(v.x), h1 = __float2bfloat16(v.y);
    __nv_bfloat16 h2 = __float2bfloat16(v.z), h3 = __float2bfloat16(v.w);
    __nv_bfloat16 l0 = __float2bfloat16(v.x - __bfloat162float(h0));
    __nv_bfloat16 l1 = __float2bfloat16(v.y - __bfloat162float(h1));
    __nv_bfloat16 l2 = __float2bfloat16(v.z - __bfloat162float(h2));
    __nv_bfloat16 l3 = __float2bfloat16(v.w - __bfloat162float(h3));
    __nv_bfloat162 hA = __halves2bfloat162(h0, h1), hB = __halves2bfloat162(h2, h3);
    __nv_bfloat162 lA = __halves2bfloat162(l0, l1), lB = __halves2bfloat162(l2, l3);
    size_t base = (size_t)r * 3 * K + k;
    __nv_bfloat162* o0 = (__nv_bfloat162*)(out + base);
    __nv_bfloat162* o1 = (__nv_bfloat162*)(out + base + K);
    __nv_bfloat162* o2 = (__nv_bfloat162*)(out + base + 2 * K);
    o0[0] = hA; o0[1] = hB;
    o1[0] = lA; o1[1] = lB;
    o2[0] = hA; o2[1] = hB;
}

// fp32 [K,N] -> fp32 [N,K]
__global__ void transpose_kernel(const float* __restrict__ in, float* __restrict__ out,
                                 int K, int N) {
    __shared__ float t[32][33];
    int n0 = blockIdx.x * 32, k0 = blockIdx.y * 32;
    int x = threadIdx.x, y = threadIdx.y;
    #pragma unroll
    for (int r = y; r < 32; r += 8)
        t[r][x] = in[(size_t)(k0 + r) * N + n0 + x];
    __syncthreads();
    #pragma unroll
    for (int r = y; r < 32; r += 8)
        out[(size_t)(n0 + r) * K + k0 + x] = t[x][r];
}

// Wq/Wk/Wv (H,D,DH) -> fp32 [1536,512] transposed ([n][d])
__global__ void repack_qkvT_kernel(const float* __restrict__ Wq, const float* __restrict__ Wk,
                                   const float* __restrict__ Wv, float* __restrict__ out) {
    int idx = blockIdx.x * blockDim.x + threadIdx.x;
    if (idx >= QKVN * DDIM) return;
    int n = idx / DDIM, d = idx % DDIM;
    int which = n / DDIM;
    int col = n % DDIM;
    int h = col / DHH, e = col % DHH;
    const float* W = (which == 0) ? Wq : (which == 1) ? Wk : Wv;
    out[idx] = W[((size_t)h * DDIM + d) * DHH + e];
}

// ---------------- LayerNorm fused with A-split (hi,hi,lo) ----------------
__global__ __launch_bounds__(128) void ln_split_kernel(const float* __restrict__ x,
                                                       const float* __restrict__ g,
                                                       const float* __restrict__ b,
                                                       __nv_bfloat16* __restrict__ out) {
    int row = blockIdx.x;
    int t = threadIdx.x;
    const float4* xr = (const float4*)(x + (size_t)row * DDIM);
    float4 v = xr[t];
    float s = v.x + v.y + v.z + v.w;
    float q = v.x * v.x + v.y * v.y + v.z * v.z + v.w * v.w;
    #pragma unroll
    for (int off = 16; off; off >>= 1) {
        s += __shfl_xor_sync(0xffffffffu, s, off);
        q += __shfl_xor_sync(0xffffffffu, q, off);
    }
    __shared__ float ss[4], qs[4];
    if ((t & 31) == 0) { ss[t >> 5] = s; qs[t >> 5] = q; }
    __syncthreads();
    s = ss[0] + ss[1] + ss[2] + ss[3];
    q = qs[0] + qs[1] + qs[2] + qs[3];
    float mean = s * (1.0f / DDIM);
    float var  = q * (1.0f / DDIM) - mean * mean;
    float inv  = rsqrtf(var + 1e-5f);
    float4 gv = ((const float4*)g)[t];
    float4 bv = ((const float4*)b)[t];
    float4 ov;
    ov.x = (v.x - mean) * inv * gv.x + bv.x;
    ov.y = (v.y - mean) * inv * gv.y + bv.y;
    ov.z = (v.z - mean) * inv * gv.z + bv.z;
    ov.w = (v.w - mean) * inv * gv.w + bv.w;
    split_store4(out, (size_t)row * 3 * DDIM + t * 4, DDIM, ov.x, ov.y, ov.z, ov.w);
}

// ---------------- HMMA GEMM: C[8192,N] = A'[8192,K3] @ B'[N,K3]^T ----------------
// 128x128 CTA tile, 8 warps (warp tile 32x64), K chunks of 64 bf16, double buffer.
#define GEMM_SMEM (2 * 32768)

__global__ __launch_bounds__(256) void mma_gemm(const __nv_bfloat16* __restrict__ A,
                                                const __nv_bfloat16* __restrict__ B,
                                                const float* __restrict__ bias,
                                                const float* __restrict__ res,
                                                float* __restrict__ C,
                                                __nv_bfloat16* __restrict__ Cs,
                                                int N, int K3, int relu) {
    extern __shared__ __align__(1024) char smem[];
    const uint32_t sb = smem_u32(smem);
    const int tid = threadIdx.x;
    const int wid = tid >> 5, lane = tid & 31;
    const int brow = blockIdx.y << 7, bcol = blockIdx.x << 7;

    const int nchunk = K3 >> 6;
    const int lrow = tid >> 1;              // 0..127
    const int lseg = (tid & 1) << 5;        // 0 or 32 elems
    const __nv_bfloat16* Ap = A + (size_t)(brow + lrow) * K3 + lseg;
    const __nv_bfloat16* Bp = B + (size_t)(bcol + lrow) * K3 + lseg;
    const uint32_t so = lrow * 128 + (lseg << 1);

    // warp tiling: 4 warps along M (32 rows each), 2 along N (64 cols each)
    const int wm = (wid & 3) << 5;
    const int wn = (wid >> 2) << 6;
    // ldmatrix lane address components
    const int a_roff = lane & 15;
    const int a_cext = (lane & 16) ? 16 : 0;
    const int b_roff = (lane & 7) + ((lane & 16) ? 8 : 0);
    const int b_cext = (lane & 8) ? 16 : 0;

    float acc[2][8][4];
    #pragma unroll
    for (int mi = 0; mi < 2; mi++)
        #pragma unroll
        for (int nj = 0; nj < 8; nj++)
            #pragma unroll
            for (int u = 0; u < 4; u++) acc[mi][nj][u] = 0.0f;

    // preload chunk 0 into buffer 0
    {
        const uint4* ag = (const uint4*)Ap;
        const uint4* bg = (const uint4*)Bp;
        #pragma unroll
        for (int u = 0; u < 4; u++) {
            uint4 av = ag[u], bv = bg[u];
            uint32_t bo = so + (u << 4);
            uint32_t sw = bo ^ ((bo >> 3) & 0x70);
            asm volatile("st.shared.v4.b32 [%0], {%1,%2,%3,%4};"
                         :: "r"(sb + sw), "r"(av.x), "r"(av.y), "r"(av.z), "r"(av.w) : "memory");
            asm volatile("st.shared.v4.b32 [%0], {%1,%2,%3,%4};"
                         :: "r"(sb + 16384 + sw), "r"(bv.x), "r"(bv.y), "r"(bv.z), "r"(bv.w) : "memory");
        }
    }
    __syncthreads();

    for (int c = 0; c < nchunk; c++) {
        const uint32_t sa = sb + (c & 1) * 32768;
        const uint32_t sB = sa + 16384;

        uint4 na[1], nb[1];
        const bool more = (c + 1 < nchunk);
        uint4 pa0, pa1, pa2, pa3, pb0, pb1, pb2, pb3;
        if (more) {
            const uint4* ag = (const uint4*)(Ap + ((size_t)(c + 1) << 6));
            const uint4* bg = (const uint4*)(Bp + ((size_t)(c + 1) << 6));
            pa0 = ag[0]; pa1 = ag[1]; pa2 = ag[2]; pa3 = ag[3];
            pb0 = bg[0]; pb1 = bg[1]; pb2 = bg[2]; pb3 = bg[3];
        }
        (void)na; (void)nb;

        #pragma unroll
        for (int k = 0; k < 4; k++) {
            const int cb0 = k << 5;      // k*16 elems * 2B
            uint32_t afr[2][4];
            #pragma unroll
            for (int mi = 0; mi < 2; mi++) {
                int row = wm + (mi << 4) + a_roff;
                uint32_t addr = sa + row * 128 + ((cb0 + a_cext) ^ ((row & 7) << 4));
                LDSM4(afr[mi], addr);
            }
            uint32_t bfr[4][4];
            #pragma unroll
            for (int g = 0; g < 4; g++) {
                int row = wn + (g << 4) + b_roff;
                uint32_t addr = sB + row * 128 + ((cb0 + b_cext) ^ ((row & 7) << 4));
                LDSM4(bfr[g], addr);
            }
            #pragma unroll
            for (int mi = 0; mi < 2; mi++)
                #pragma unroll
                for (int nj = 0; nj < 8; nj++)
                    mma16816(acc[mi][nj], afr[mi],
                             bfr[nj >> 1][(nj & 1) << 1], bfr[nj >> 1][((nj & 1) << 1) + 1]);
        }

        if (more) {
            __syncthreads();
            const uint32_t da = sb + ((c + 1) & 1) * 32768;
            const uint32_t dB = da + 16384;
            uint4 avs[4] = {pa0, pa1, pa2, pa3};
            uint4 bvs[4] = {pb0, pb1, pb2, pb3};
            #pragma unroll
            for (int u = 0; u < 4; u++) {
                uint32_t bo = so + (u << 4);
                uint32_t sw = bo ^ ((bo >> 3) & 0x70);
                asm volatile("st.shared.v4.b32 [%0], {%1,%2,%3,%4};"
                             :: "r"(da + sw), "r"(avs[u].x), "r"(avs[u].y), "r"(avs[u].z), "r"(avs[u].w) : "memory");
                asm volatile("st.shared.v4.b32 [%0], {%1,%2,%3,%4};"
                             :: "r"(dB + sw), "r"(bvs[u].x), "r"(bvs[u].y), "r"(bvs[u].z), "r"(bvs[u].w) : "memory");
            }
            __syncthreads();
        }
    }

    // ---------------- epilogue ----------------
    const int qr = lane >> 2;            // 0..7
    const int qc = (lane & 3) << 1;      // 0,2,4,6
    #pragma unroll
    for (int mi = 0; mi < 2; mi++) {
        #pragma unroll
        for (int half = 0; half < 2; half++) {
            const int m = brow + wm + (mi << 4) + qr + (half << 3);
            #pragma unroll
            for (int nj = 0; nj < 8; nj++) {
                const int col = bcol + wn + (nj << 3) + qc;
                float v0 = acc[mi][nj][half * 2 + 0];
                float v1 = acc[mi][nj][half * 2 + 1];
                if (bias) {
                    float2 bb = *(const float2*)(bias + col);
                    v0 += bb.x; v1 += bb.y;
                }
                if (relu) { v0 = fmaxf(v0, 0.0f); v1 = fmaxf(v1, 0.0f); }
                if (res) {
                    float2 rr = *(const float2*)(res + (size_t)m * N + col);
                    v0 += rr.x; v1 += rr.y;
                }
                if (Cs) split_store2(Cs, (size_t)m * 3 * N + col, N, v0, v1);
                else    *(float2*)(C + (size_t)m * N + col) = make_float2(v0, v1);
            }
        }
    }
}

// ---------------- flash attention (writes split A directly) ----------------
#define NEG_BIG (-1e30f)
#define ATTN_SMEM (3 * 64 * 68 * 4)

__global__ __launch_bounds__(256) void attn_kernel(const float* __restrict__ qkv,
                                                   __nv_bfloat16* __restrict__ o_split) {
    extern __shared__ float sm[];
    float (*Qt)[68] = (float(*)[68])sm;
    float (*Kt)[68] = (float(*)[68])(sm + 64 * 68);
    float (*Vs)[68] = (float(*)[68])(sm + 2 * 64 * 68);

    const int it = blockIdx.x;
    const int h  = blockIdx.y;
    const int b  = blockIdx.z;
    const int qbase = it * 64;
    const int tid = threadIdx.x;
    const int tx = tid & 15, ty = tid >> 4;
    const float scale = 0.044194173824159216f;  // 512^-0.5

    {
        int r  = tid >> 2;
        int c0 = (tid & 3) * 16;
        const float* src = qkv + (size_t)(b * TT + qbase + r) * QKVN + h * DHH + c0;
        #pragma unroll
        for (int u = 0; u < 16; u += 4) {
            float4 v = *(const float4*)(src + u);
            Qt[c0 + u + 0][r] = v.x; Qt[c0 + u + 1][r] = v.y;
            Qt[c0 + u + 2][r] = v.z; Qt[c0 + u + 3][r] = v.w;
        }
    }

    float oacc[4][4];
    float m[4], l[4];
    #pragma unroll
    for (int i = 0; i < 4; i++) {
        m[i] = NEG_BIG; l[i] = 0.0f;
        #pragma unroll
        for (int j = 0; j < 4; j++) oacc[i][j] = 0.0f;
    }

    for (int jt = 0; jt <= it; jt++) {
        const int kbase = jt * 64;
        {
            int r  = tid >> 2;
            int c0 = (tid & 3) * 16;
            const float* ksrc = qkv + (size_t)(b * TT + kbase + r) * QKVN + DDIM + h * DHH + c0;
            const float* vsrc = ksrc + DDIM;
            #pragma unroll
            for (int u = 0; u < 16; u += 4) {
                float4 kv = *(const float4*)(ksrc + u);
                float4 vv = *(const float4*)(vsrc + u);
                Kt[c0 + u + 0][r] = kv.x; Kt[c0 + u + 1][r] = kv.y;
                Kt[c0 + u + 2][r] = kv.z; Kt[c0 + u + 3][r] = kv.w;
                Vs[r][c0 + u + 0] = vv.x; Vs[r][c0 + u + 1] = vv.y;
                Vs[r][c0 + u + 2] = vv.z; Vs[r][c0 + u + 3] = vv.w;
            }
        }
        __syncthreads();

        float s[4][4];
        #pragma unroll
        for (int i = 0; i < 4; i++)
            #pragma unroll
            for (int j = 0; j < 4; j++) s[i][j] = 0.0f;
        #pragma unroll 4
        for (int e = 0; e < 64; e++) {
            float4 q4 = *(const float4*)&Qt[e][ty * 4];
            float4 k4 = *(const float4*)&Kt[e][tx * 4];
            float qv[4] = {q4.x, q4.y, q4.z, q4.w};
            float kv[4] = {k4.x, k4.y, k4.z, k4.w};
            #pragma unroll
            for (int i = 0; i < 4; i++)
                #pragma unroll
                for (int j = 0; j < 4; j++)
                    s[i][j] += qv[i] * kv[j];
        }
        __syncthreads();

        const bool diag = (jt == it);
        #pragma unroll
        for (int i = 0; i < 4; i++) {
            int rloc = ty * 4 + i;
            float mt = NEG_BIG;
            #pragma unroll
            for (int j = 0; j < 4; j++) {
                float v = s[i][j] * scale;
                if (diag && (tx * 4 + j > rloc)) v = NEG_BIG;
                s[i][j] = v;
                mt = fmaxf(mt, v);
            }
            #pragma unroll
            for (int off = 1; off < 16; off <<= 1)
                mt = fmaxf(mt, __shfl_xor_sync(0xffffffffu, mt, off));
            float newm = fmaxf(m[i], mt);
            float alpha = __expf(m[i] - newm);
            float rs = 0.0f;
            #pragma unroll
            for (int j = 0; j < 4; j++) {
                float p = __expf(s[i][j] - newm);
                s[i][j] = p;
                rs += p;
            }
            #pragma unroll
            for (int off = 1; off < 16; off <<= 1)
                rs += __shfl_xor_sync(0xffffffffu, rs, off);
            l[i] = l[i] * alpha + rs;
            m[i] = newm;
            #pragma unroll
            for (int j = 0; j < 4; j++) oacc[i][j] *= alpha;
        }

        #pragma unroll
        for (int i = 0; i < 4; i++)
            #pragma unroll
            for (int j = 0; j < 4; j++)
                Kt[ty * 4 + i][tx * 4 + j] = s[i][j];
        __syncthreads();

        #pragma unroll 4
        for (int c = 0; c < 64; c++) {
            float4 v4 = *(const float4*)&Vs[c][tx * 4];
            float vv[4] = {v4.x, v4.y, v4.z, v4.w};
            float pv[4];
            #pragma unroll
            for (int i = 0; i < 4; i++) pv[i] = Kt[ty * 4 + i][c];
            #pragma unroll
            for (int i = 0; i < 4; i++)
                #pragma unroll
                for (int j = 0; j < 4; j++)
                    oacc[i][j] += pv[i] * vv[j];
        }
        __syncthreads();
    }

    #pragma unroll
    for (int i = 0; i < 4; i++) {
        float invl = 1.0f / l[i];
        int gr = b * TT + qbase + ty * 4 + i;
        split_store4(o_split, (size_t)gr * 3 * DDIM + h * DHH + tx * 4, DDIM,
                     oacc[i][0] * invl, oacc[i][1] * invl,
                     oacc[i][2] * invl, oacc[i][3] * invl);
    }
}

// ---------------- launch ----------------
extern "C" void kernel_launch(void* const* d_in, const int* in_sizes, int n_in,
                              void* d_out, int out_size) {
    const float* x     = (const float*)d_in[0];
    const float* ln1_g = (const float*)d_in[1];
    const float* ln1_b = (const float*)d_in[2];
    const float* Wq    = (const float*)d_in[3];
    const float* Wk    = (const float*)d_in[4];
    const float* Wv    = (const float*)d_in[5];
    const float* Wproj = (const float*)d_in[6];
    const float* bproj = (const float*)d_in[7];
    const float* W1    = (const float*)d_in[8];
    const float* b1    = (const float*)d_in[9];
    const float* W2    = (const float*)d_in[10];
    const float* b2    = (const float*)d_in[11];
    float* out = (float*)d_out;

    float *p_qkv, *p_x1, *p_wt;
    __nv_bfloat16 *p_abf, *p_abf2, *p_bbf;
    cudaGetSymbolAddress((void**)&p_qkv,  g_qkv);
    cudaGetSymbolAddress((void**)&p_x1,   g_x1);
    cudaGetSymbolAddress((void**)&p_wt,   g_wt);
    cudaGetSymbolAddress((void**)&p_abf,  g_abf);
    cudaGetSymbolAddress((void**)&p_abf2, g_abf2);
    cudaGetSymbolAddress((void**)&p_bbf,  g_bbf);

    cudaFuncSetAttribute(attn_kernel, cudaFuncAttributeMaxDynamicSharedMemorySize, ATTN_SMEM);
    cudaFuncSetAttribute(mma_gemm, cudaFuncAttributeMaxDynamicSharedMemorySize, GEMM_SMEM);

    const int SPLIT_TB = 256;
    #define SPLIT_GRID(n) (((n) / 4 + SPLIT_TB - 1) / SPLIT_TB)

    // ---- attention sublayer ----
    ln_split_kernel<<<BT, 128>>>(x, ln1_g, ln1_b, p_abf);
    repack_qkvT_kernel<<<(QKVN * DDIM + 255) / 256, 256>>>(Wq, Wk, Wv, p_wt);
    splitB_kernel<<<SPLIT_GRID(QKVN * DDIM), SPLIT_TB>>>(p_wt, p_bbf, QKVN * DDIM, DDIM);
    mma_gemm<<<dim3(QKVN / 128, BT / 128), 256, GEMM_SMEM>>>(
        p_abf, p_bbf, nullptr, nullptr, p_qkv, nullptr, QKVN, 3 * DDIM, 0);
    attn_kernel<<<dim3(TT / 64, HH, BB), 256, ATTN_SMEM>>>(p_qkv, p_abf);

    transpose_kernel<<<dim3(DDIM / 32, DDIM / 32), dim3(32, 8)>>>(Wproj, p_wt, DDIM, DDIM);
    splitB_kernel<<<SPLIT_GRID(DDIM * DDIM), SPLIT_TB>>>(p_wt, p_bbf, DDIM * DDIM, DDIM);
    mma_gemm<<<dim3(DDIM / 128, BT / 128), 256, GEMM_SMEM>>>(
        p_abf, p_bbf, bproj, x, p_x1, nullptr, DDIM, 3 * DDIM, 0);

    // ---- FFN sublayer ----
    ln_split_kernel<<<BT, 128>>>(p_x1, ln1_g, ln1_b, p_abf);
    transpose_kernel<<<dim3(FFD / 32, DDIM / 32), dim3(32, 8)>>>(W1, p_wt, DDIM, FFD);
    splitB_kernel<<<SPLIT_GRID(FFD * DDIM), SPLIT_TB>>>(p_wt, p_bbf, FFD * DDIM, DDIM);
    mma_gemm<<<dim3(FFD / 128, BT / 128), 256, GEMM_SMEM>>>(
        p_abf, p_bbf, b1, nullptr, nullptr, p_abf2, FFD, 3 * DDIM, 1);

    transpose_kernel<<<dim3(DDIM / 32, FFD / 32), dim3(32, 8)>>>(W2, p_wt, FFD, DDIM);
    splitB_kernel<<<SPLIT_GRID(DDIM * FFD), SPLIT_TB>>>(p_wt, p_bbf, DDIM * FFD, FFD);
    mma_gemm<<<dim3(DDIM / 128, BT / 128), 256, GEMM_SMEM>>>(
        p_abf2, p_bbf, b2, p_x1, out, nullptr, DDIM, 3 * FFD, 0);
}

// round 7
// speedup vs baseline: 3.2634x; 1.3338x over previous
#include <cuda_runtime.h>
#include <cuda_bf16.h>
#include <cstdint>

#define BB   4
#define TT   2048
#define DDIM 512
#define HH   8
#define DHH  64
#define BT   8192
#define FFD  2048
#define QKVN 1536
#define ATT_SCALE 0.044194173824159216f   // 512^-0.5

// ---------------- scratch ----------------
__device__ float g_x1  [(size_t)BT * DDIM];
__device__ float g_wt  [(size_t)FFD * DDIM];             // transposed weight staging (fp32)
__device__ __nv_bfloat16 g_abf [(size_t)BT * 3 * DDIM];  // split activations (A layout)
__device__ __nv_bfloat16 g_abf2[(size_t)BT * 3 * FFD];   // split ff1 (A layout)
__device__ __nv_bfloat16 g_bbf [(size_t)FFD * 3 * DDIM]; // split weights [N,3K] (B layout)
__device__ __nv_bfloat16 g_qs  [(size_t)BT * QKVN];      // q split (hi,hi,lo), scaled, [tok][h*192+e']
__device__ __nv_bfloat16 g_ks  [(size_t)BT * QKVN];      // k split (hi,lo,hi)
__device__ __nv_bfloat16 g_vs  [(size_t)BT * 1024];      // v hi|lo  [tok][h*128 + e(/64)]

// ---------------- helpers ----------------
__device__ __forceinline__ uint32_t smem_u32(const void* p) {
    uint32_t a;
    asm("{ .reg .u64 t; cvta.to.shared.u64 t, %1; cvt.u32.u64 %0, t; }" : "=r"(a) : "l"(p));
    return a;
}
__device__ __forceinline__ uint32_t pack_bf16x2(__nv_bfloat16 a, __nv_bfloat16 b) {
    return (uint32_t)__bfloat16_as_ushort(a) | ((uint32_t)__bfloat16_as_ushort(b) << 16);
}

#define LDSM4(d, addr)                                                                  \
    asm volatile("ldmatrix.sync.aligned.m8n8.x4.shared.b16 {%0,%1,%2,%3}, [%4];"        \
                 : "=r"((d)[0]), "=r"((d)[1]), "=r"((d)[2]), "=r"((d)[3]) : "r"(addr))
#define LDSM4T(d, addr)                                                                 \
    asm volatile("ldmatrix.sync.aligned.m8n8.x4.trans.shared.b16 {%0,%1,%2,%3}, [%4];"  \
                 : "=r"((d)[0]), "=r"((d)[1]), "=r"((d)[2]), "=r"((d)[3]) : "r"(addr))

__device__ __forceinline__ void mma16816(float* c, const uint32_t* a,
                                         uint32_t b0, uint32_t b1) {
    asm volatile(
        "mma.sync.aligned.m16n8k16.row.col.f32.bf16.bf16.f32 "
        "{%0,%1,%2,%3}, {%4,%5,%6,%7}, {%8,%9}, {%0,%1,%2,%3};"
        : "+f"(c[0]), "+f"(c[1]), "+f"(c[2]), "+f"(c[3])
        : "r"(a[0]), "r"(a[1]), "r"(a[2]), "r"(a[3]), "r"(b0), "r"(b1));
}

#define CPASYNC16(dst, src)                                                             \
    asm volatile("cp.async.cg.shared.global [%0], [%1], 16;" :: "r"(dst), "l"(src) : "memory")

__device__ __forceinline__ void split_store4(__nv_bfloat16* base, size_t off, int K,
                                             float a, float b, float c, float d) {
    __nv_bfloat16 h0 = __float2bfloat16(a), h1 = __float2bfloat16(b);
    __nv_bfloat16 h2 = __float2bfloat16(c), h3 = __float2bfloat16(d);
    __nv_bfloat16 l0 = __float2bfloat16(a - __bfloat162float(h0));
    __nv_bfloat16 l1 = __float2bfloat16(b - __bfloat162float(h1));
    __nv_bfloat16 l2 = __float2bfloat16(c - __bfloat162float(h2));
    __nv_bfloat16 l3 = __float2bfloat16(d - __bfloat162float(h3));
    __nv_bfloat162 hA = __halves2bfloat162(h0, h1), hB = __halves2bfloat162(h2, h3);
    __nv_bfloat162 lA = __halves2bfloat162(l0, l1), lB = __halves2bfloat162(l2, l3);
    __nv_bfloat162* p0 = (__nv_bfloat162*)(base + off);
    __nv_bfloat162* p1 = (__nv_bfloat162*)(base + off + K);
    __nv_bfloat162* p2 = (__nv_bfloat162*)(base + off + 2 * (size_t)K);
    p0[0] = hA; p0[1] = hB;
    p1[0] = hA; p1[1] = hB;
    p2[0] = lA; p2[1] = lB;
}

// A layout pair: hi@off, hi@off+K, lo@off+2K
__device__ __forceinline__ void split_store2(__nv_bfloat16* base, size_t off, int K,
                                             float a, float b) {
    __nv_bfloat16 h0 = __float2bfloat16(a), h1 = __float2bfloat16(b);
    __nv_bfloat16 l0 = __float2bfloat16(a - __bfloat162float(h0));
    __nv_bfloat16 l1 = __float2bfloat16(b - __bfloat162float(h1));
    *(__nv_bfloat162*)(base + off)                 = __halves2bfloat162(h0, h1);
    *(__nv_bfloat162*)(base + off + K)             = __halves2bfloat162(h0, h1);
    *(__nv_bfloat162*)(base + off + 2 * (size_t)K) = __halves2bfloat162(l0, l1);
}

// B layout pair: hi@off, lo@off+K, hi@off+2K
__device__ __forceinline__ void splitB2(__nv_bfloat16* base, size_t off, int K,
                                        float a, float b) {
    __nv_bfloat16 h0 = __float2bfloat16(a), h1 = __float2bfloat16(b);
    __nv_bfloat16 l0 = __float2bfloat16(a - __bfloat162float(h0));
    __nv_bfloat16 l1 = __float2bfloat16(b - __bfloat162float(h1));
    *(__nv_bfloat162*)(base + off)                 = __halves2bfloat162(h0, h1);
    *(__nv_bfloat162*)(base + off + K)             = __halves2bfloat162(l0, l1);
    *(__nv_bfloat162*)(base + off + 2 * (size_t)K) = __halves2bfloat162(h0, h1);
}

// ---------------- prep kernels ----------------
__global__ void splitB_kernel(const float* __restrict__ in, __nv_bfloat16* __restrict__ out,
                              int total, int K) {
    int i = (blockIdx.x * blockDim.x + threadIdx.x) * 4;
    if (i >= total) return;
    int r = i / K, k = i % K;
    float4 v = *(const float4*)(in + i);
    size_t base = (size_t)r * 3 * K + k;
    splitB2(out, base, K, v.x, v.y);
    splitB2(out, base + 2, K, v.z, v.w);
}

__global__ void transpose_kernel(const float* __restrict__ in, float* __restrict__ out,
                                 int K, int N) {
    __shared__ float t[32][33];
    int n0 = blockIdx.x * 32, k0 = blockIdx.y * 32;
    int x = threadIdx.x, y = threadIdx.y;
    #pragma unroll
    for (int r = y; r < 32; r += 8)
        t[r][x] = in[(size_t)(k0 + r) * N + n0 + x];
    __syncthreads();
    #pragma unroll
    for (int r = y; r < 32; r += 8)
        out[(size_t)(n0 + r) * K + k0 + x] = t[x][r];
}

__global__ void repack_qkvT_kernel(const float* __restrict__ Wq, const float* __restrict__ Wk,
                                   const float* __restrict__ Wv, float* __restrict__ out) {
    int idx = blockIdx.x * blockDim.x + threadIdx.x;
    if (idx >= QKVN * DDIM) return;
    int n = idx / DDIM, d = idx % DDIM;
    int which = n / DDIM;
    int col = n % DDIM;
    int h = col / DHH, e = col % DHH;
    const float* W = (which == 0) ? Wq : (which == 1) ? Wk : Wv;
    out[idx] = W[((size_t)h * DDIM + d) * DHH + e];
}

// ---------------- LayerNorm fused with A-split ----------------
__global__ __launch_bounds__(128) void ln_split_kernel(const float* __restrict__ x,
                                                       const float* __restrict__ g,
                                                       const float* __restrict__ b,
                                                       __nv_bfloat16* __restrict__ out) {
    int row = blockIdx.x;
    int t = threadIdx.x;
    const float4* xr = (const float4*)(x + (size_t)row * DDIM);
    float4 v = xr[t];
    float s = v.x + v.y + v.z + v.w;
    float q = v.x * v.x + v.y * v.y + v.z * v.z + v.w * v.w;
    #pragma unroll
    for (int off = 16; off; off >>= 1) {
        s += __shfl_xor_sync(0xffffffffu, s, off);
        q += __shfl_xor_sync(0xffffffffu, q, off);
    }
    __shared__ float ss[4], qs[4];
    if ((t & 31) == 0) { ss[t >> 5] = s; qs[t >> 5] = q; }
    __syncthreads();
    s = ss[0] + ss[1] + ss[2] + ss[3];
    q = qs[0] + qs[1] + qs[2] + qs[3];
    float mean = s * (1.0f / DDIM);
    float var  = q * (1.0f / DDIM) - mean * mean;
    float inv  = rsqrtf(var + 1e-5f);
    float4 gv = ((const float4*)g)[t];
    float4 bv = ((const float4*)b)[t];
    float4 ov;
    ov.x = (v.x - mean) * inv * gv.x + bv.x;
    ov.y = (v.y - mean) * inv * gv.y + bv.y;
    ov.z = (v.z - mean) * inv * gv.z + bv.z;
    ov.w = (v.w - mean) * inv * gv.w + bv.w;
    split_store4(out, (size_t)row * 3 * DDIM + t * 4, DDIM, ov.x, ov.y, ov.z, ov.w);
}

// ---------------- HMMA GEMM with cp.async ----------------
// mode 0: fp32 C (+bias/relu/res).  mode 1: Cs = A-split [M][3N].  mode 2: qkv split outputs.
#define GEMM_SMEM (2 * 32768)

__global__ __launch_bounds__(256) void mma_gemm(const __nv_bfloat16* __restrict__ A,
                                                const __nv_bfloat16* __restrict__ B,
                                                const float* __restrict__ bias,
                                                const float* __restrict__ res,
                                                float* __restrict__ C,
                                                __nv_bfloat16* __restrict__ Cs,
                                                __nv_bfloat16* __restrict__ Ko,
                                                __nv_bfloat16* __restrict__ Vo,
                                                int N, int K3, int relu, int mode) {
    extern __shared__ __align__(1024) char smem[];
    const uint32_t sb = smem_u32(smem);
    const int tid = threadIdx.x;
    const int wid = tid >> 5, lane = tid & 31;
    const int brow = blockIdx.y << 7, bcol = blockIdx.x << 7;

    const int nchunk = K3 >> 6;
    const int lrow = tid >> 1;
    const int lseg = (tid & 1) << 5;
    const __nv_bfloat16* Ap = A + (size_t)(brow + lrow) * K3 + lseg;
    const __nv_bfloat16* Bp = B + (size_t)(bcol + lrow) * K3 + lseg;
    const uint32_t so = lrow * 128 + (lseg << 1);
    uint32_t sw_off[4];
    #pragma unroll
    for (int u = 0; u < 4; u++) {
        uint32_t bo = so + (u << 4);
        sw_off[u] = bo ^ ((bo >> 3) & 0x70);
    }

    const int wm = (wid & 3) << 5;
    const int wn = (wid >> 2) << 6;
    const int a_roff = lane & 15;
    const int a_cext = (lane & 16) ? 16 : 0;
    const int b_roff = (lane & 7) + ((lane & 16) ? 8 : 0);
    const int b_cext = (lane & 8) ? 16 : 0;

    float acc[2][8][4];
    #pragma unroll
    for (int mi = 0; mi < 2; mi++)
        #pragma unroll
        for (int nj = 0; nj < 8; nj++)
            #pragma unroll
            for (int u = 0; u < 4; u++) acc[mi][nj][u] = 0.0f;

    // issue chunk 0
    #pragma unroll
    for (int u = 0; u < 4; u++) {
        CPASYNC16(sb + sw_off[u], (const char*)Ap + u * 16);
        CPASYNC16(sb + 16384 + sw_off[u], (const char*)Bp + u * 16);
    }
    asm volatile("cp.async.commit_group;" ::: "memory");

    for (int c = 0; c < nchunk; c++) {
        asm volatile("cp.async.wait_group 0;" ::: "memory");
        __syncthreads();
        if (c + 1 < nchunk) {
            const uint32_t da = sb + ((c + 1) & 1) * 32768;
            const char* ag = (const char*)(Ap + ((size_t)(c + 1) << 6));
            const char* bg = (const char*)(Bp + ((size_t)(c + 1) << 6));
            #pragma unroll
            for (int u = 0; u < 4; u++) {
                CPASYNC16(da + sw_off[u], ag + u * 16);
                CPASYNC16(da + 16384 + sw_off[u], bg + u * 16);
            }
            asm volatile("cp.async.commit_group;" ::: "memory");
        }
        const uint32_t sa = sb + (c & 1) * 32768;
        const uint32_t sB = sa + 16384;
        #pragma unroll
        for (int k = 0; k < 4; k++) {
            const int cb0 = k << 5;
            uint32_t afr[2][4];
            #pragma unroll
            for (int mi = 0; mi < 2; mi++) {
                int row = wm + (mi << 4) + a_roff;
                LDSM4(afr[mi], sa + row * 128 + ((cb0 + a_cext) ^ ((row & 7) << 4)));
            }
            uint32_t bfr[4][4];
            #pragma unroll
            for (int g = 0; g < 4; g++) {
                int row = wn + (g << 4) + b_roff;
                LDSM4(bfr[g], sB + row * 128 + ((cb0 + b_cext) ^ ((row & 7) << 4)));
            }
            #pragma unroll
            for (int mi = 0; mi < 2; mi++)
                #pragma unroll
                for (int nj = 0; nj < 8; nj++)
                    mma16816(acc[mi][nj], afr[mi],
                             bfr[nj >> 1][(nj & 1) << 1], bfr[nj >> 1][((nj & 1) << 1) + 1]);
        }
    }

    // ---------------- epilogue ----------------
    const int qr = lane >> 2;
    const int qc = (lane & 3) << 1;
    #pragma unroll
    for (int mi = 0; mi < 2; mi++) {
        #pragma unroll
        for (int half = 0; half < 2; half++) {
            const int m = brow + wm + (mi << 4) + qr + (half << 3);
            #pragma unroll
            for (int nj = 0; nj < 8; nj++) {
                const int col = bcol + wn + (nj << 3) + qc;
                float v0 = acc[mi][nj][half * 2 + 0];
                float v1 = acc[mi][nj][half * 2 + 1];
                if (bias) {
                    float2 bb = *(const float2*)(bias + col);
                    v0 += bb.x; v1 += bb.y;
                }
                if (relu) { v0 = fmaxf(v0, 0.0f); v1 = fmaxf(v1, 0.0f); }
                if (res) {
                    float2 rr = *(const float2*)(res + (size_t)m * N + col);
                    v0 += rr.x; v1 += rr.y;
                }
                if (mode == 0) {
                    *(float2*)(C + (size_t)m * N + col) = make_float2(v0, v1);
                } else if (mode == 1) {
                    split_store2(Cs, (size_t)m * 3 * N + col, N, v0, v1);
                } else {
                    if (col < 512) {          // q: scale + A-split into [tok][h*192+e]
                        int hh = col >> 6, e = col & 63;
                        split_store2(Cs, (size_t)m * QKVN + hh * 192 + e, 64,
                                     v0 * ATT_SCALE, v1 * ATT_SCALE);
                    } else if (col < 1024) {  // k: B-split
                        int cc = col - 512;
                        int hh = cc >> 6, e = cc & 63;
                        splitB2(Ko, (size_t)m * QKVN + hh * 192 + e, 64, v0, v1);
                    } else {                  // v: hi|lo
                        int cc = col - 1024;
                        int hh = cc >> 6, e = cc & 63;
                        size_t off = (size_t)m * 1024 + hh * 128 + e;
                        __nv_bfloat16 h0 = __float2bfloat16(v0), h1 = __float2bfloat16(v1);
                        __nv_bfloat16 l0 = __float2bfloat16(v0 - __bfloat162float(h0));
                        __nv_bfloat16 l1 = __float2bfloat16(v1 - __bfloat162float(h1));
                        *(__nv_bfloat162*)(Vo + off)      = __halves2bfloat162(h0, h1);
                        *(__nv_bfloat162*)(Vo + off + 64) = __halves2bfloat162(l0, l1);
                    }
                }
            }
        }
    }
}

// ---------------- mma flash attention ----------------
// CTA: (qtile 64, h, b); 4 warps; warp owns 16 q rows.
// smem: Qs[64][200] | Ks[64][200] | Ps[64][200] | Vs[192][72]   (bf16)
#define ATT_SMEM 104448
#define QK_STRIDE 400   // bytes per row (200 bf16)
#define V_STRIDE  144   // bytes per row (72 bf16)

__global__ __launch_bounds__(128) void attn_mma(const __nv_bfloat16* __restrict__ qs,
                                                const __nv_bfloat16* __restrict__ ksg,
                                                const __nv_bfloat16* __restrict__ vsg,
                                                __nv_bfloat16* __restrict__ o_split) {
    extern __shared__ __align__(16) char smc[];
    const uint32_t Q0 = smem_u32(smc);
    const uint32_t K0 = Q0 + 25600;
    const uint32_t P0 = Q0 + 51200;
    const uint32_t V0 = Q0 + 76800;

    const int it = gridDim.x - 1 - blockIdx.x;   // big tiles first
    const int h = blockIdx.y, b = blockIdx.z;
    const int qbase = it * 64;
    const int tid = threadIdx.x;
    const int wq = tid >> 5;
    const int lane = tid & 31;

    // load Q tile (split, scaled) once: rows q, 192 cols (96 bf16 = 12 uint4 per thread-half)
    {
        int row = tid >> 1, seg = (tid & 1) * 96;
        const uint4* src = (const uint4*)(qs + (size_t)(b * TT + qbase + row) * QKVN + h * 192 + seg);
        uint32_t dst = Q0 + row * QK_STRIDE + seg * 2;
        #pragma unroll
        for (int u = 0; u < 12; u++) {
            uint4 v = src[u];
            asm volatile("st.shared.v4.b32 [%0], {%1,%2,%3,%4};"
                         :: "r"(dst + u * 16), "r"(v.x), "r"(v.y), "r"(v.z), "r"(v.w) : "memory");
        }
    }

    float acco[8][4];
    #pragma unroll
    for (int t = 0; t < 8; t++)
        #pragma unroll
        for (int u = 0; u < 4; u++) acco[t][u] = 0.0f;
    float m0 = -1e30f, m1 = -1e30f, l0 = 0.0f, l1 = 0.0f;
    const int r0 = lane >> 2;
    const int qlr0 = wq * 16 + r0;       // local q row (0..63)
    const int qlr1 = qlr0 + 8;
    const int a_roff = lane & 15;
    const int a_cext = (lane & 16) ? 16 : 0;
    const int b_roff = (lane & 7) + ((lane & 16) ? 8 : 0);
    const int b_cext = (lane & 8) ? 16 : 0;

    for (int jt = 0; jt <= it; jt++) {
        const int kb = jt * 64;
        __syncthreads();   // prev iter's readers done (also orders Q stores on first iter)
        // K tile: rows key, 192 cols
        {
            int row = tid >> 1, seg = (tid & 1) * 96;
            const uint4* src = (const uint4*)(ksg + (size_t)(b * TT + kb + row) * QKVN + h * 192 + seg);
            uint32_t dst = K0 + row * QK_STRIDE + seg * 2;
            #pragma unroll
            for (int u = 0; u < 12; u++) {
                uint4 v = src[u];
                asm volatile("st.shared.v4.b32 [%0], {%1,%2,%3,%4};"
                             :: "r"(dst + u * 16), "r"(v.x), "r"(v.y), "r"(v.z), "r"(v.w) : "memory");
            }
        }
        // V tile: 192 rows (hi|lo|hi), 64 cols e
        for (int r = tid; r < 192; r += 128) {
            int key = r & 63;
            int seg2 = (r >= 64 && r < 128) ? 64 : 0;
            const uint4* src = (const uint4*)(vsg + (size_t)(b * TT + kb + key) * 1024 + h * 128 + seg2);
            uint32_t dst = V0 + r * V_STRIDE;
            #pragma unroll
            for (int u = 0; u < 8; u++) {
                uint4 v = src[u];
                asm volatile("st.shared.v4.b32 [%0], {%1,%2,%3,%4};"
                             :: "r"(dst + u * 16), "r"(v.x), "r"(v.y), "r"(v.z), "r"(v.w) : "memory");
            }
        }
        __syncthreads();

        // S = Q' @ K'^T  (m16 per warp, n64, k192)
        float accs[8][4];
        #pragma unroll
        for (int t = 0; t < 8; t++)
            #pragma unroll
            for (int u = 0; u < 4; u++) accs[t][u] = 0.0f;
        #pragma unroll
        for (int ks = 0; ks < 12; ks++) {
            uint32_t af[4];
            {
                int row = wq * 16 + a_roff;
                LDSM4(af, Q0 + row * QK_STRIDE + ks * 32 + a_cext);
            }
            uint32_t bf[4][4];
            #pragma unroll
            for (int g = 0; g < 4; g++) {
                int row = g * 16 + b_roff;
                LDSM4(bf[g], K0 + row * QK_STRIDE + ks * 32 + b_cext);
            }
            #pragma unroll
            for (int nj = 0; nj < 8; nj++)
                mma16816(accs[nj], af,
                         bf[nj >> 1][(nj & 1) << 1], bf[nj >> 1][((nj & 1) << 1) + 1]);
        }

        // softmax update
        if (jt == it) {
            #pragma unroll
            for (int t = 0; t < 8; t++) {
                int c0 = t * 8 + (lane & 3) * 2;
                if (c0     > qlr0) accs[t][0] = -1e30f;
                if (c0 + 1 > qlr0) accs[t][1] = -1e30f;
                if (c0     > qlr1) accs[t][2] = -1e30f;
                if (c0 + 1 > qlr1) accs[t][3] = -1e30f;
            }
        }
        float mx0 = -1e30f, mx1 = -1e30f;
        #pragma unroll
        for (int t = 0; t < 8; t++) {
            mx0 = fmaxf(mx0, fmaxf(accs[t][0], accs[t][1]));
            mx1 = fmaxf(mx1, fmaxf(accs[t][2], accs[t][3]));
        }
        mx0 = fmaxf(mx0, __shfl_xor_sync(0xffffffffu, mx0, 1));
        mx0 = fmaxf(mx0, __shfl_xor_sync(0xffffffffu, mx0, 2));
        mx1 = fmaxf(mx1, __shfl_xor_sync(0xffffffffu, mx1, 1));
        mx1 = fmaxf(mx1, __shfl_xor_sync(0xffffffffu, mx1, 2));
        float nm0 = fmaxf(m0, mx0), nm1 = fmaxf(m1, mx1);
        float al0 = __expf(m0 - nm0), al1 = __expf(m1 - nm1);
        float s0 = 0.0f, s1 = 0.0f;
        #pragma unroll
        for (int t = 0; t < 8; t++) {
            float p00 = __expf(accs[t][0] - nm0);
            float p01 = __expf(accs[t][1] - nm0);
            float p10 = __expf(accs[t][2] - nm1);
            float p11 = __expf(accs[t][3] - nm1);
            s0 += p00 + p01; s1 += p10 + p11;
            int cb = (t * 8 + (lane & 3) * 2) * 2;  // byte col in Ps
            {
                __nv_bfloat16 h0 = __float2bfloat16(p00), h1 = __float2bfloat16(p01);
                __nv_bfloat16 q0 = __float2bfloat16(p00 - __bfloat162float(h0));
                __nv_bfloat16 q1 = __float2bfloat16(p01 - __bfloat162float(h1));
                uint32_t hv = pack_bf16x2(h0, h1);
                uint32_t lv = pack_bf16x2(q0, q1);
                uint32_t ad = P0 + qlr0 * QK_STRIDE + cb;
                asm volatile("st.shared.b32 [%0], %1;" :: "r"(ad), "r"(hv) : "memory");
                asm volatile("st.shared.b32 [%0], %1;" :: "r"(ad + 128), "r"(hv) : "memory");
                asm volatile("st.shared.b32 [%0], %1;" :: "r"(ad + 256), "r"(lv) : "memory");
            }
            {
                __nv_bfloat16 h0 = __float2bfloat16(p10), h1 = __float2bfloat16(p11);
                __nv_bfloat16 q0 = __float2bfloat16(p10 - __bfloat162float(h0));
                __nv_bfloat16 q1 = __float2bfloat16(p11 - __bfloat162float(h1));
                uint32_t hv = pack_bf16x2(h0, h1);
                uint32_t lv = pack_bf16x2(q0, q1);
                uint32_t ad = P0 + qlr1 * QK_STRIDE + cb;
                asm volatile("st.shared.b32 [%0], %1;" :: "r"(ad), "r"(hv) : "memory");
                asm volatile("st.shared.b32 [%0], %1;" :: "r"(ad + 128), "r"(hv) : "memory");
                asm volatile("st.shared.b32 [%0], %1;" :: "r"(ad + 256), "r"(lv) : "memory");
            }
        }
        s0 += __shfl_xor_sync(0xffffffffu, s0, 1);
        s0 += __shfl_xor_sync(0xffffffffu, s0, 2);
        s1 += __shfl_xor_sync(0xffffffffu, s1, 1);
        s1 += __shfl_xor_sync(0xffffffffu, s1, 2);
        l0 = l0 * al0 + s0;
        l1 = l1 * al1 + s1;
        m0 = nm0; m1 = nm1;
        #pragma unroll
        for (int t = 0; t < 8; t++) {
            acco[t][0] *= al0; acco[t][1] *= al0;
            acco[t][2] *= al1; acco[t][3] *= al1;
        }
        __syncwarp();

        // O += P' @ V'   (k192 over split keys, n64 = e)
        #pragma unroll
        for (int ks = 0; ks < 12; ks++) {
            uint32_t af[4];
            {
                int row = wq * 16 + a_roff;
                LDSM4(af, P0 + row * QK_STRIDE + ks * 32 + a_cext);
            }
            uint32_t bf[4][4];
            #pragma unroll
            for (int g = 0; g < 4; g++) {
                int row = ks * 16 + (lane & 15);
                LDSM4T(bf[g], V0 + row * V_STRIDE + g * 32 + ((lane & 16) ? 16 : 0));
            }
            #pragma unroll
            for (int nj = 0; nj < 8; nj++)
                mma16816(acco[nj], af,
                         bf[nj >> 1][(nj & 1) << 1], bf[nj >> 1][((nj & 1) << 1) + 1]);
        }
    }

    // epilogue: divide by l, write A-split o into o_split [tok][3*512]
    const float i0 = 1.0f / l0, i1 = 1.0f / l1;
    const int gr0 = b * TT + qbase + qlr0;
    const int gr1 = b * TT + qbase + qlr1;
    #pragma unroll
    for (int t = 0; t < 8; t++) {
        int e = t * 8 + (lane & 3) * 2;
        split_store2(o_split, (size_t)gr0 * 3 * DDIM + h * 64 + e, DDIM,
                     acco[t][0] * i0, acco[t][1] * i0);
        split_store2(o_split, (size_t)gr1 * 3 * DDIM + h * 64 + e, DDIM,
                     acco[t][2] * i1, acco[t][3] * i1);
    }
}

// ---------------- launch ----------------
extern "C" void kernel_launch(void* const* d_in, const int* in_sizes, int n_in,
                              void* d_out, int out_size) {
    const float* x     = (const float*)d_in[0];
    const float* ln1_g = (const float*)d_in[1];
    const float* ln1_b = (const float*)d_in[2];
    const float* Wq    = (const float*)d_in[3];
    const float* Wk    = (const float*)d_in[4];
    const float* Wv    = (const float*)d_in[5];
    const float* Wproj = (const float*)d_in[6];
    const float* bproj = (const float*)d_in[7];
    const float* W1    = (const float*)d_in[8];
    const float* b1    = (const float*)d_in[9];
    const float* W2    = (const float*)d_in[10];
    const float* b2    = (const float*)d_in[11];
    float* out = (float*)d_out;

    float *p_x1, *p_wt;
    __nv_bfloat16 *p_abf, *p_abf2, *p_bbf, *p_qs, *p_ks, *p_vs;
    cudaGetSymbolAddress((void**)&p_x1,   g_x1);
    cudaGetSymbolAddress((void**)&p_wt,   g_wt);
    cudaGetSymbolAddress((void**)&p_abf,  g_abf);
    cudaGetSymbolAddress((void**)&p_abf2, g_abf2);
    cudaGetSymbolAddress((void**)&p_bbf,  g_bbf);
    cudaGetSymbolAddress((void**)&p_qs,   g_qs);
    cudaGetSymbolAddress((void**)&p_ks,   g_ks);
    cudaGetSymbolAddress((void**)&p_vs,   g_vs);

    cudaFuncSetAttribute(attn_mma, cudaFuncAttributeMaxDynamicSharedMemorySize, ATT_SMEM);
    cudaFuncSetAttribute(mma_gemm, cudaFuncAttributeMaxDynamicSharedMemorySize, GEMM_SMEM);

    const int SPLIT_TB = 256;
    #define SPLIT_GRID(n) (((n) / 4 + SPLIT_TB - 1) / SPLIT_TB)

    // ---- attention sublayer ----
    ln_split_kernel<<<BT, 128>>>(x, ln1_g, ln1_b, p_abf);
    repack_qkvT_kernel<<<(QKVN * DDIM + 255) / 256, 256>>>(Wq, Wk, Wv, p_wt);
    splitB_kernel<<<SPLIT_GRID(QKVN * DDIM), SPLIT_TB>>>(p_wt, p_bbf, QKVN * DDIM, DDIM);
    mma_gemm<<<dim3(QKVN / 128, BT / 128), 256, GEMM_SMEM>>>(
        p_abf, p_bbf, nullptr, nullptr, nullptr, p_qs, p_ks, p_vs, QKVN, 3 * DDIM, 0, 2);
    attn_mma<<<dim3(TT / 64, HH, BB), 128, ATT_SMEM>>>(p_qs, p_ks, p_vs, p_abf);

    transpose_kernel<<<dim3(DDIM / 32, DDIM / 32), dim3(32, 8)>>>(Wproj, p_wt, DDIM, DDIM);
    splitB_kernel<<<SPLIT_GRID(DDIM * DDIM), SPLIT_TB>>>(p_wt, p_bbf, DDIM * DDIM, DDIM);
    mma_gemm<<<dim3(DDIM / 128, BT / 128), 256, GEMM_SMEM>>>(
        p_abf, p_bbf, bproj, x, p_x1, nullptr, nullptr, nullptr, DDIM, 3 * DDIM, 0, 0);

    // ---- FFN sublayer ----
    ln_split_kernel<<<BT, 128>>>(p_x1, ln1_g, ln1_b, p_abf);
    transpose_kernel<<<dim3(FFD / 32, DDIM / 32), dim3(32, 8)>>>(W1, p_wt, DDIM, FFD);
    splitB_kernel<<<SPLIT_GRID(FFD * DDIM), SPLIT_TB>>>(p_wt, p_bbf, FFD * DDIM, DDIM);
    mma_gemm<<<dim3(FFD / 128, BT / 128), 256, GEMM_SMEM>>>(
        p_abf, p_bbf, b1, nullptr, nullptr, p_abf2, nullptr, nullptr, FFD, 3 * DDIM, 1, 1);

    transpose_kernel<<<dim3(DDIM / 32, FFD / 32), dim3(32, 8)>>>(W2, p_wt, FFD, DDIM);
    splitB_kernel<<<SPLIT_GRID(DDIM * FFD), SPLIT_TB>>>(p_wt, p_bbf, DDIM * FFD, FFD);
    mma_gemm<<<dim3(DDIM / 128, BT / 128), 256, GEMM_SMEM>>>(
        p_abf2, p_bbf, b2, p_x1, out, nullptr, nullptr, nullptr, DDIM, 3 * FFD, 0, 0);
}

// round 9
// speedup vs baseline: 3.6562x; 1.1204x over previous
#include <cuda_runtime.h>
#include <cuda_bf16.h>
#include <cstdint>

#define BB   4
#define TT   2048
#define DDIM 512
#define HH   8
#define DHH  64
#define BT   8192
#define FFD  2048
#define QKVN 1536
#define ATT_SCALE 0.044194173824159216f   // 512^-0.5

// ---------------- scratch ----------------
__device__ float g_x1  [(size_t)BT * DDIM];
__device__ float g_wt  [(size_t)FFD * DDIM];             // transposed weight staging (fp32)
__device__ __nv_bfloat16 g_abf [(size_t)BT * 3 * DDIM];  // split activations (A layout)
__device__ __nv_bfloat16 g_abf2[(size_t)BT * 3 * FFD];   // split ff1 (A layout)
__device__ __nv_bfloat16 g_bbf [(size_t)FFD * 3 * DDIM]; // split weights [N,3K] (B layout)
__device__ __nv_bfloat16 g_qs  [(size_t)BT * QKVN];      // q split (hi,hi,lo), scaled
__device__ __nv_bfloat16 g_ks  [(size_t)BT * QKVN];      // k split (hi,lo,hi)
__device__ __nv_bfloat16 g_vs  [(size_t)BT * 1024];      // v hi|lo  [tok][h*128 + part*64 + e]

// ---------------- helpers ----------------
__device__ __forceinline__ uint32_t smem_u32(const void* p) {
    uint32_t a;
    asm("{ .reg .u64 t; cvta.to.shared.u64 t, %1; cvt.u32.u64 %0, t; }" : "=r"(a) : "l"(p));
    return a;
}
__device__ __forceinline__ uint32_t pack_bf16x2(__nv_bfloat16 a, __nv_bfloat16 b) {
    return (uint32_t)__bfloat16_as_ushort(a) | ((uint32_t)__bfloat16_as_ushort(b) << 16);
}

#define LDSM4(d, addr)                                                                  \
    asm volatile("ldmatrix.sync.aligned.m8n8.x4.shared.b16 {%0,%1,%2,%3}, [%4];"        \
                 : "=r"((d)[0]), "=r"((d)[1]), "=r"((d)[2]), "=r"((d)[3]) : "r"(addr))
#define LDSM4T(d, addr)                                                                 \
    asm volatile("ldmatrix.sync.aligned.m8n8.x4.trans.shared.b16 {%0,%1,%2,%3}, [%4];"  \
                 : "=r"((d)[0]), "=r"((d)[1]), "=r"((d)[2]), "=r"((d)[3]) : "r"(addr))

__device__ __forceinline__ void mma16816(float* c, const uint32_t* a,
                                         uint32_t b0, uint32_t b1) {
    asm volatile(
        "mma.sync.aligned.m16n8k16.row.col.f32.bf16.bf16.f32 "
        "{%0,%1,%2,%3}, {%4,%5,%6,%7}, {%8,%9}, {%0,%1,%2,%3};"
        : "+f"(c[0]), "+f"(c[1]), "+f"(c[2]), "+f"(c[3])
        : "r"(a[0]), "r"(a[1]), "r"(a[2]), "r"(a[3]), "r"(b0), "r"(b1));
}

#define CPASYNC16(dst, src)                                                             \
    asm volatile("cp.async.cg.shared.global [%0], [%1], 16;" :: "r"(dst), "l"(src) : "memory")
#define CPCOMMIT() asm volatile("cp.async.commit_group;" ::: "memory")

__device__ __forceinline__ void split_store4(__nv_bfloat16* base, size_t off, int K,
                                             float a, float b, float c, float d) {
    __nv_bfloat16 h0 = __float2bfloat16(a), h1 = __float2bfloat16(b);
    __nv_bfloat16 h2 = __float2bfloat16(c), h3 = __float2bfloat16(d);
    __nv_bfloat16 l0 = __float2bfloat16(a - __bfloat162float(h0));
    __nv_bfloat16 l1 = __float2bfloat16(b - __bfloat162float(h1));
    __nv_bfloat16 l2 = __float2bfloat16(c - __bfloat162float(h2));
    __nv_bfloat16 l3 = __float2bfloat16(d - __bfloat162float(h3));
    __nv_bfloat162 hA = __halves2bfloat162(h0, h1), hB = __halves2bfloat162(h2, h3);
    __nv_bfloat162 lA = __halves2bfloat162(l0, l1), lB = __halves2bfloat162(l2, l3);
    __nv_bfloat162* p0 = (__nv_bfloat162*)(base + off);
    __nv_bfloat162* p1 = (__nv_bfloat162*)(base + off + K);
    __nv_bfloat162* p2 = (__nv_bfloat162*)(base + off + 2 * (size_t)K);
    p0[0] = hA; p0[1] = hB;
    p1[0] = hA; p1[1] = hB;
    p2[0] = lA; p2[1] = lB;
}

// A layout pair: hi@off, hi@off+K, lo@off+2K
__device__ __forceinline__ void split_store2(__nv_bfloat16* base, size_t off, int K,
                                             float a, float b) {
    __nv_bfloat16 h0 = __float2bfloat16(a), h1 = __float2bfloat16(b);
    __nv_bfloat16 l0 = __float2bfloat16(a - __bfloat162float(h0));
    __nv_bfloat16 l1 = __float2bfloat16(b - __bfloat162float(h1));
    *(__nv_bfloat162*)(base + off)                 = __halves2bfloat162(h0, h1);
    *(__nv_bfloat162*)(base + off + K)             = __halves2bfloat162(h0, h1);
    *(__nv_bfloat162*)(base + off + 2 * (size_t)K) = __halves2bfloat162(l0, l1);
}

// B layout pair: hi@off, lo@off+K, hi@off+2K
__device__ __forceinline__ void splitB2(__nv_bfloat16* base, size_t off, int K,
                                        float a, float b) {
    __nv_bfloat16 h0 = __float2bfloat16(a), h1 = __float2bfloat16(b);
    __nv_bfloat16 l0 = __float2bfloat16(a - __bfloat162float(h0));
    __nv_bfloat16 l1 = __float2bfloat16(b - __bfloat162float(h1));
    *(__nv_bfloat162*)(base + off)                 = __halves2bfloat162(h0, h1);
    *(__nv_bfloat162*)(base + off + K)             = __halves2bfloat162(l0, l1);
    *(__nv_bfloat162*)(base + off + 2 * (size_t)K) = __halves2bfloat162(h0, h1);
}

// ---------------- prep kernels ----------------
__global__ void splitB_kernel(const float* __restrict__ in, __nv_bfloat16* __restrict__ out,
                              int total, int K) {
    int i = (blockIdx.x * blockDim.x + threadIdx.x) * 4;
    if (i >= total) return;
    int r = i / K, k = i % K;
    float4 v = *(const float4*)(in + i);
    size_t base = (size_t)r * 3 * K + k;
    splitB2(out, base, K, v.x, v.y);
    splitB2(out, base + 2, K, v.z, v.w);
}

__global__ void transpose_kernel(const float* __restrict__ in, float* __restrict__ out,
                                 int K, int N) {
    __shared__ float t[32][33];
    int n0 = blockIdx.x * 32, k0 = blockIdx.y * 32;
    int x = threadIdx.x, y = threadIdx.y;
    #pragma unroll
    for (int r = y; r < 32; r += 8)
        t[r][x] = in[(size_t)(k0 + r) * N + n0 + x];
    __syncthreads();
    #pragma unroll
    for (int r = y; r < 32; r += 8)
        out[(size_t)(n0 + r) * K + k0 + x] = t[x][r];
}

__global__ void repack_qkvT_kernel(const float* __restrict__ Wq, const float* __restrict__ Wk,
                                   const float* __restrict__ Wv, float* __restrict__ out) {
    int idx = blockIdx.x * blockDim.x + threadIdx.x;
    if (idx >= QKVN * DDIM) return;
    int n = idx / DDIM, d = idx % DDIM;
    int which = n / DDIM;
    int col = n % DDIM;
    int h = col / DHH, e = col % DHH;
    const float* W = (which == 0) ? Wq : (which == 1) ? Wk : Wv;
    out[idx] = W[((size_t)h * DDIM + d) * DHH + e];
}

// ---------------- LayerNorm fused with A-split ----------------
__global__ __launch_bounds__(128) void ln_split_kernel(const float* __restrict__ x,
                                                       const float* __restrict__ g,
                                                       const float* __restrict__ b,
                                                       __nv_bfloat16* __restrict__ out) {
    int row = blockIdx.x;
    int t = threadIdx.x;
    const float4* xr = (const float4*)(x + (size_t)row * DDIM);
    float4 v = xr[t];
    float s = v.x + v.y + v.z + v.w;
    float q = v.x * v.x + v.y * v.y + v.z * v.z + v.w * v.w;
    #pragma unroll
    for (int off = 16; off; off >>= 1) {
        s += __shfl_xor_sync(0xffffffffu, s, off);
        q += __shfl_xor_sync(0xffffffffu, q, off);
    }
    __shared__ float ss[4], qs[4];
    if ((t & 31) == 0) { ss[t >> 5] = s; qs[t >> 5] = q; }
    __syncthreads();
    s = ss[0] + ss[1] + ss[2] + ss[3];
    q = qs[0] + qs[1] + qs[2] + qs[3];
    float mean = s * (1.0f / DDIM);
    float var  = q * (1.0f / DDIM) - mean * mean;
    float inv  = rsqrtf(var + 1e-5f);
    float4 gv = ((const float4*)g)[t];
    float4 bv = ((const float4*)b)[t];
    float4 ov;
    ov.x = (v.x - mean) * inv * gv.x + bv.x;
    ov.y = (v.y - mean) * inv * gv.y + bv.y;
    ov.z = (v.z - mean) * inv * gv.z + bv.z;
    ov.w = (v.w - mean) * inv * gv.w + bv.w;
    split_store4(out, (size_t)row * 3 * DDIM + t * 4, DDIM, ov.x, ov.y, ov.z, ov.w);
}

// ---------------- HMMA GEMM, 3-stage cp.async pipeline ----------------
// mode 0: fp32 C (+bias/relu/res).  mode 1: Cs = A-split [M][3N].  mode 2: qkv split outputs.
#define GEMM_SMEM (3 * 32768)

__global__ __launch_bounds__(256) void mma_gemm(const __nv_bfloat16* __restrict__ A,
                                                const __nv_bfloat16* __restrict__ B,
                                                const float* __restrict__ bias,
                                                const float* __restrict__ res,
                                                float* __restrict__ C,
                                                __nv_bfloat16* __restrict__ Cs,
                                                __nv_bfloat16* __restrict__ Ko,
                                                __nv_bfloat16* __restrict__ Vo,
                                                int N, int K3, int relu, int mode) {
    extern __shared__ __align__(1024) char smem[];
    const uint32_t sb = smem_u32(smem);
    const int tid = threadIdx.x;
    const int wid = tid >> 5, lane = tid & 31;
    const int brow = blockIdx.y << 7, bcol = blockIdx.x << 7;

    const int nchunk = K3 >> 6;
    const int lrow = tid >> 1;
    const int lseg = (tid & 1) << 5;
    const __nv_bfloat16* Ap = A + (size_t)(brow + lrow) * K3 + lseg;
    const __nv_bfloat16* Bp = B + (size_t)(bcol + lrow) * K3 + lseg;
    const uint32_t so = lrow * 128 + (lseg << 1);
    uint32_t sw_off[4];
    #pragma unroll
    for (int u = 0; u < 4; u++) {
        uint32_t bo = so + (u << 4);
        sw_off[u] = bo ^ ((bo >> 3) & 0x70);
    }

    const int wm = (wid & 3) << 5;
    const int wn = (wid >> 2) << 6;
    const int a_roff = lane & 15;
    const int a_cext = (lane & 16) ? 16 : 0;
    const int b_roff = (lane & 7) + ((lane & 16) ? 8 : 0);
    const int b_cext = (lane & 8) ? 16 : 0;

    auto issue_chunk = [&](int cc) {
        const uint32_t da = sb + (uint32_t)(cc % 3) * 32768u;
        const char* ag = (const char*)(Ap + ((size_t)cc << 6));
        const char* bg = (const char*)(Bp + ((size_t)cc << 6));
        #pragma unroll
        for (int u = 0; u < 4; u++) {
            CPASYNC16(da + sw_off[u], ag + u * 16);
            CPASYNC16(da + 16384 + sw_off[u], bg + u * 16);
        }
        CPCOMMIT();
    };

    float acc[2][8][4];
    #pragma unroll
    for (int mi = 0; mi < 2; mi++)
        #pragma unroll
        for (int nj = 0; nj < 8; nj++)
            #pragma unroll
            for (int u = 0; u < 4; u++) acc[mi][nj][u] = 0.0f;

    issue_chunk(0);
    issue_chunk(1);

    for (int c = 0; c < nchunk; c++) {
        if (c + 1 < nchunk) asm volatile("cp.async.wait_group 1;" ::: "memory");
        else                asm volatile("cp.async.wait_group 0;" ::: "memory");
        __syncthreads();
        if (c + 2 < nchunk) issue_chunk(c + 2);

        const uint32_t sa = sb + (uint32_t)(c % 3) * 32768u;
        const uint32_t sB = sa + 16384;
        #pragma unroll
        for (int k = 0; k < 4; k++) {
            const int cb0 = k << 5;
            uint32_t afr[2][4];
            #pragma unroll
            for (int mi = 0; mi < 2; mi++) {
                int row = wm + (mi << 4) + a_roff;
                LDSM4(afr[mi], sa + row * 128 + ((cb0 + a_cext) ^ ((row & 7) << 4)));
            }
            uint32_t bfr[4][4];
            #pragma unroll
            for (int g = 0; g < 4; g++) {
                int row = wn + (g << 4) + b_roff;
                LDSM4(bfr[g], sB + row * 128 + ((cb0 + b_cext) ^ ((row & 7) << 4)));
            }
            #pragma unroll
            for (int mi = 0; mi < 2; mi++)
                #pragma unroll
                for (int nj = 0; nj < 8; nj++)
                    mma16816(acc[mi][nj], afr[mi],
                             bfr[nj >> 1][(nj & 1) << 1], bfr[nj >> 1][((nj & 1) << 1) + 1]);
        }
    }

    // ---------------- epilogue ----------------
    const int qr = lane >> 2;
    const int qc = (lane & 3) << 1;
    #pragma unroll
    for (int mi = 0; mi < 2; mi++) {
        #pragma unroll
        for (int half = 0; half < 2; half++) {
            const int m = brow + wm + (mi << 4) + qr + (half << 3);
            #pragma unroll
            for (int nj = 0; nj < 8; nj++) {
                const int col = bcol + wn + (nj << 3) + qc;
                float v0 = acc[mi][nj][half * 2 + 0];
                float v1 = acc[mi][nj][half * 2 + 1];
                if (bias) {
                    float2 bb = *(const float2*)(bias + col);
                    v0 += bb.x; v1 += bb.y;
                }
                if (relu) { v0 = fmaxf(v0, 0.0f); v1 = fmaxf(v1, 0.0f); }
                if (res) {
                    float2 rr = *(const float2*)(res + (size_t)m * N + col);
                    v0 += rr.x; v1 += rr.y;
                }
                if (mode == 0) {
                    *(float2*)(C + (size_t)m * N + col) = make_float2(v0, v1);
                } else if (mode == 1) {
                    split_store2(Cs, (size_t)m * 3 * N + col, N, v0, v1);
                } else {
                    if (col < 512) {          // q: scale + A-split
                        int hh = col >> 6, e = col & 63;
                        split_store2(Cs, (size_t)m * QKVN + hh * 192 + e, 64,
                                     v0 * ATT_SCALE, v1 * ATT_SCALE);
                    } else if (col < 1024) {  // k: B-split
                        int cc = col - 512;
                        int hh = cc >> 6, e = cc & 63;
                        splitB2(Ko, (size_t)m * QKVN + hh * 192 + e, 64, v0, v1);
                    } else {                  // v: hi|lo
                        int cc = col - 1024;
                        int hh = cc >> 6, e = cc & 63;
                        size_t off = (size_t)m * 1024 + hh * 128 + e;
                        __nv_bfloat16 h0 = __float2bfloat16(v0), h1 = __float2bfloat16(v1);
                        __nv_bfloat16 l0 = __float2bfloat16(v0 - __bfloat162float(h0));
                        __nv_bfloat16 l1 = __float2bfloat16(v1 - __bfloat162float(h1));
                        *(__nv_bfloat162*)(Vo + off)      = __halves2bfloat162(h0, h1);
                        *(__nv_bfloat162*)(Vo + off + 64) = __halves2bfloat162(l0, l1);
                    }
                }
            }
        }
    }
}

// ---------------- mma flash attention (register P, cp.async K/V) ----------------
// smem: Qs[64][200] | Ks[64][200] | Vs 2 x [128][72]   (bf16)
#define ATT_SMEM 88064
#define QK_STRIDE 400   // bytes per row (200 bf16)
#define V_STRIDE  144   // bytes per row (72 bf16)
#define V_BUF     18432 // 128 * 144

__global__ __launch_bounds__(128) void attn_mma(const __nv_bfloat16* __restrict__ qs,
                                                const __nv_bfloat16* __restrict__ ksg,
                                                const __nv_bfloat16* __restrict__ vsg,
                                                __nv_bfloat16* __restrict__ o_split) {
    extern __shared__ __align__(16) char smc[];
    const uint32_t Q0 = smem_u32(smc);
    const uint32_t K0 = Q0 + 25600;
    const uint32_t V0 = Q0 + 51200;

    const int it = gridDim.x - 1 - blockIdx.x;   // big tiles first
    const int h = blockIdx.y, b = blockIdx.z;
    const int qbase = it * 64;
    const int tid = threadIdx.x;
    const int wq = tid >> 5;
    const int lane = tid & 31;

    auto issue_K = [&](int jt2) {
        int row = tid >> 1, seg = (tid & 1) * 96;
        const char* src = (const char*)(ksg + (size_t)(b * TT + jt2 * 64 + row) * QKVN + h * 192 + seg);
        uint32_t dst = K0 + row * QK_STRIDE + seg * 2;
        #pragma unroll
        for (int u = 0; u < 12; u++) CPASYNC16(dst + u * 16, src + u * 16);
        CPCOMMIT();
    };
    auto issue_V = [&](int jt2) {
        int key = tid & 63, part = tid >> 6;           // 128 threads -> 128 rows
        const char* src = (const char*)(vsg + (size_t)(b * TT + jt2 * 64 + key) * 1024 + h * 128 + part * 64);
        uint32_t dst = V0 + (uint32_t)(jt2 & 1) * V_BUF + tid * V_STRIDE;
        #pragma unroll
        for (int u = 0; u < 8; u++) CPASYNC16(dst + u * 16, src + u * 16);
        CPCOMMIT();
    };

    issue_K(0);
    issue_V(0);

    // load Q tile (split, scaled) once: 64 rows x 192 cols
    {
        int row = tid >> 1, seg = (tid & 1) * 96;
        const uint4* src = (const uint4*)(qs + (size_t)(b * TT + qbase + row) * QKVN + h * 192 + seg);
        uint32_t dst = Q0 + row * QK_STRIDE + seg * 2;
        #pragma unroll
        for (int u = 0; u < 12; u++) {
            uint4 v = src[u];
            asm volatile("st.shared.v4.b32 [%0], {%1,%2,%3,%4};"
                         :: "r"(dst + u * 16), "r"(v.x), "r"(v.y), "r"(v.z), "r"(v.w) : "memory");
        }
    }

    float acco[8][4];
    #pragma unroll
    for (int t = 0; t < 8; t++)
        #pragma unroll
        for (int u = 0; u < 4; u++) acco[t][u] = 0.0f;
    float m0 = -1e30f, m1 = -1e30f, l0 = 0.0f, l1 = 0.0f;
    const int r0 = lane >> 2;
    const int qlr0 = wq * 16 + r0;
    const int qlr1 = qlr0 + 8;
    const int a_roff = lane & 15;
    const int a_cext = (lane & 16) ? 16 : 0;
    const int b_roff = (lane & 7) + ((lane & 16) ? 8 : 0);
    const int b_cext = (lane & 8) ? 16 : 0;
    const int v_cext = (lane & 16) ? 16 : 0;

    for (int jt = 0; jt <= it; jt++) {
        // K(jt) arrived (newest group V(jt) may still be in flight)
        asm volatile("cp.async.wait_group 1;" ::: "memory");
        __syncthreads();

        // S = Q' @ K'^T  (m16 per warp, n64, k192)
        float accs[8][4];
        #pragma unroll
        for (int t = 0; t < 8; t++)
            #pragma unroll
            for (int u = 0; u < 4; u++) accs[t][u] = 0.0f;
        #pragma unroll
        for (int ks = 0; ks < 12; ks++) {
            uint32_t af[4];
            {
                int row = wq * 16 + a_roff;
                LDSM4(af, Q0 + row * QK_STRIDE + ks * 32 + a_cext);
            }
            uint32_t bf[4][4];
            #pragma unroll
            for (int g = 0; g < 4; g++) {
                int row = g * 16 + b_roff;
                LDSM4(bf[g], K0 + row * QK_STRIDE + ks * 32 + b_cext);
            }
            #pragma unroll
            for (int nj = 0; nj < 8; nj++)
                mma16816(accs[nj], af,
                         bf[nj >> 1][(nj & 1) << 1], bf[nj >> 1][((nj & 1) << 1) + 1]);
        }
        __syncthreads();   // all warps done reading K(jt)
        if (jt < it) { issue_K(jt + 1); issue_V(jt + 1); }

        // softmax (register-resident)
        if (jt == it) {
            #pragma unroll
            for (int t = 0; t < 8; t++) {
                int c0 = t * 8 + (lane & 3) * 2;
                if (c0     > qlr0) accs[t][0] = -1e30f;
                if (c0 + 1 > qlr0) accs[t][1] = -1e30f;
                if (c0     > qlr1) accs[t][2] = -1e30f;
                if (c0 + 1 > qlr1) accs[t][3] = -1e30f;
            }
        }
        float mx0 = -1e30f, mx1 = -1e30f;
        #pragma unroll
        for (int t = 0; t < 8; t++) {
            mx0 = fmaxf(mx0, fmaxf(accs[t][0], accs[t][1]));
            mx1 = fmaxf(mx1, fmaxf(accs[t][2], accs[t][3]));
        }
        mx0 = fmaxf(mx0, __shfl_xor_sync(0xffffffffu, mx0, 1));
        mx0 = fmaxf(mx0, __shfl_xor_sync(0xffffffffu, mx0, 2));
        mx1 = fmaxf(mx1, __shfl_xor_sync(0xffffffffu, mx1, 1));
        mx1 = fmaxf(mx1, __shfl_xor_sync(0xffffffffu, mx1, 2));
        float nm0 = fmaxf(m0, mx0), nm1 = fmaxf(m1, mx1);
        float al0 = __expf(m0 - nm0), al1 = __expf(m1 - nm1);
        float s0 = 0.0f, s1 = 0.0f;
        #pragma unroll
        for (int t = 0; t < 8; t++) {
            accs[t][0] = __expf(accs[t][0] - nm0);
            accs[t][1] = __expf(accs[t][1] - nm0);
            accs[t][2] = __expf(accs[t][2] - nm1);
            accs[t][3] = __expf(accs[t][3] - nm1);
            s0 += accs[t][0] + accs[t][1];
            s1 += accs[t][2] + accs[t][3];
        }
        s0 += __shfl_xor_sync(0xffffffffu, s0, 1);
        s0 += __shfl_xor_sync(0xffffffffu, s0, 2);
        s1 += __shfl_xor_sync(0xffffffffu, s1, 1);
        s1 += __shfl_xor_sync(0xffffffffu, s1, 2);
        l0 = l0 * al0 + s0;
        l1 = l1 * al1 + s1;
        m0 = nm0; m1 = nm1;
        #pragma unroll
        for (int t = 0; t < 8; t++) {
            acco[t][0] *= al0; acco[t][1] *= al0;
            acco[t][2] *= al1; acco[t][3] *= al1;
        }

        // V(jt) arrived + visible
        if (jt < it) asm volatile("cp.async.wait_group 2;" ::: "memory");
        else         asm volatile("cp.async.wait_group 0;" ::: "memory");
        __syncthreads();

        // O += Phi@Vhi + Phi@Vlo + Plo@Vhi  (register P fragments)
        const uint32_t vb = V0 + (uint32_t)(jt & 1) * V_BUF;
        #pragma unroll
        for (int t = 0; t < 4; t++) {
            // A fragments from accs (C-fragment -> A-fragment identity)
            uint32_t af_hi[4], af_lo[4];
            #pragma unroll
            for (int u = 0; u < 4; u++) {
                float pa = accs[2 * t + (u >> 1)][(u & 1) ? 2 : 0];
                float pb = accs[2 * t + (u >> 1)][(u & 1) ? 3 : 1];
                // order: af[0]=(r0, c,c+1), af[1]=(r0+8,...), af[2]=(r0,c+8..), af[3]=(r0+8,c+8..)
                (void)pa; (void)pb;
            }
            {
                __nv_bfloat16 h00 = __float2bfloat16(accs[2*t][0]);
                __nv_bfloat16 h01 = __float2bfloat16(accs[2*t][1]);
                __nv_bfloat16 h02 = __float2bfloat16(accs[2*t][2]);
                __nv_bfloat16 h03 = __float2bfloat16(accs[2*t][3]);
                __nv_bfloat16 h10 = __float2bfloat16(accs[2*t+1][0]);
                __nv_bfloat16 h11 = __float2bfloat16(accs[2*t+1][1]);
                __nv_bfloat16 h12 = __float2bfloat16(accs[2*t+1][2]);
                __nv_bfloat16 h13 = __float2bfloat16(accs[2*t+1][3]);
                af_hi[0] = pack_bf16x2(h00, h01);
                af_hi[1] = pack_bf16x2(h02, h03);
                af_hi[2] = pack_bf16x2(h10, h11);
                af_hi[3] = pack_bf16x2(h12, h13);
                af_lo[0] = pack_bf16x2(__float2bfloat16(accs[2*t][0] - __bfloat162float(h00)),
                                       __float2bfloat16(accs[2*t][1] - __bfloat162float(h01)));
                af_lo[1] = pack_bf16x2(__float2bfloat16(accs[2*t][2] - __bfloat162float(h02)),
                                       __float2bfloat16(accs[2*t][3] - __bfloat162float(h03)));
                af_lo[2] = pack_bf16x2(__float2bfloat16(accs[2*t+1][0] - __bfloat162float(h10)),
                                       __float2bfloat16(accs[2*t+1][1] - __bfloat162float(h11)));
                af_lo[3] = pack_bf16x2(__float2bfloat16(accs[2*t+1][2] - __bfloat162float(h12)),
                                       __float2bfloat16(accs[2*t+1][3] - __bfloat162float(h13)));
            }
            uint32_t bh[4][4], bl[4][4];
            #pragma unroll
            for (int g = 0; g < 4; g++) {
                int rhi = t * 16 + (lane & 15);
                LDSM4T(bh[g], vb + rhi * V_STRIDE + g * 32 + v_cext);
                LDSM4T(bl[g], vb + (64 + rhi) * V_STRIDE + g * 32 + v_cext);
            }
            #pragma unroll
            for (int nj = 0; nj < 8; nj++) {
                uint32_t bh0 = bh[nj >> 1][(nj & 1) << 1], bh1 = bh[nj >> 1][((nj & 1) << 1) + 1];
                uint32_t bl0 = bl[nj >> 1][(nj & 1) << 1], bl1 = bl[nj >> 1][((nj & 1) << 1) + 1];
                mma16816(acco[nj], af_hi, bh0, bh1);
                mma16816(acco[nj], af_hi, bl0, bl1);
                mma16816(acco[nj], af_lo, bh0, bh1);
            }
        }
    }

    // epilogue: divide by l, write A-split o into o_split [tok][3*512]
    const float i0 = 1.0f / l0, i1 = 1.0f / l1;
    const int gr0 = b * TT + qbase + qlr0;
    const int gr1 = b * TT + qbase + qlr1;
    #pragma unroll
    for (int t = 0; t < 8; t++) {
        int e = t * 8 + (lane & 3) * 2;
        split_store2(o_split, (size_t)gr0 * 3 * DDIM + h * 64 + e, DDIM,
                     acco[t][0] * i0, acco[t][1] * i0);
        split_store2(o_split, (size_t)gr1 * 3 * DDIM + h * 64 + e, DDIM,
                     acco[t][2] * i1, acco[t][3] * i1);
    }
}

// ---------------- launch ----------------
extern "C" void kernel_launch(void* const* d_in, const int* in_sizes, int n_in,
                              void* d_out, int out_size) {
    const float* x     = (const float*)d_in[0];
    const float* ln1_g = (const float*)d_in[1];
    const float* ln1_b = (const float*)d_in[2];
    const float* Wq    = (const float*)d_in[3];
    const float* Wk    = (const float*)d_in[4];
    const float* Wv    = (const float*)d_in[5];
    const float* Wproj = (const float*)d_in[6];
    const float* bproj = (const float*)d_in[7];
    const float* W1    = (const float*)d_in[8];
    const float* b1    = (const float*)d_in[9];
    const float* W2    = (const float*)d_in[10];
    const float* b2    = (const float*)d_in[11];
    float* out = (float*)d_out;

    float *p_x1, *p_wt;
    __nv_bfloat16 *p_abf, *p_abf2, *p_bbf, *p_qs, *p_ks, *p_vs;
    cudaGetSymbolAddress((void**)&p_x1,   g_x1);
    cudaGetSymbolAddress((void**)&p_wt,   g_wt);
    cudaGetSymbolAddress((void**)&p_abf,  g_abf);
    cudaGetSymbolAddress((void**)&p_abf2, g_abf2);
    cudaGetSymbolAddress((void**)&p_bbf,  g_bbf);
    cudaGetSymbolAddress((void**)&p_qs,   g_qs);
    cudaGetSymbolAddress((void**)&p_ks,   g_ks);
    cudaGetSymbolAddress((void**)&p_vs,   g_vs);

    cudaFuncSetAttribute(attn_mma, cudaFuncAttributeMaxDynamicSharedMemorySize, ATT_SMEM);
    cudaFuncSetAttribute(mma_gemm, cudaFuncAttributeMaxDynamicSharedMemorySize, GEMM_SMEM);

    const int SPLIT_TB = 256;
    #define SPLIT_GRID(n) (((n) / 4 + SPLIT_TB - 1) / SPLIT_TB)

    // ---- attention sublayer ----
    ln_split_kernel<<<BT, 128>>>(x, ln1_g, ln1_b, p_abf);
    repack_qkvT_kernel<<<(QKVN * DDIM + 255) / 256, 256>>>(Wq, Wk, Wv, p_wt);
    splitB_kernel<<<SPLIT_GRID(QKVN * DDIM), SPLIT_TB>>>(p_wt, p_bbf, QKVN * DDIM, DDIM);
    mma_gemm<<<dim3(QKVN / 128, BT / 128), 256, GEMM_SMEM>>>(
        p_abf, p_bbf, nullptr, nullptr, nullptr, p_qs, p_ks, p_vs, QKVN, 3 * DDIM, 0, 2);
    attn_mma<<<dim3(TT / 64, HH, BB), 128, ATT_SMEM>>>(p_qs, p_ks, p_vs, p_abf);

    transpose_kernel<<<dim3(DDIM / 32, DDIM / 32), dim3(32, 8)>>>(Wproj, p_wt, DDIM, DDIM);
    splitB_kernel<<<SPLIT_GRID(DDIM * DDIM), SPLIT_TB>>>(p_wt, p_bbf, DDIM * DDIM, DDIM);
    mma_gemm<<<dim3(DDIM / 128, BT / 128), 256, GEMM_SMEM>>>(
        p_abf, p_bbf, bproj, x, p_x1, nullptr, nullptr, nullptr, DDIM, 3 * DDIM, 0, 0);

    // ---- FFN sublayer ----
    ln_split_kernel<<<BT, 128>>>(p_x1, ln1_g, ln1_b, p_abf);
    transpose_kernel<<<dim3(FFD / 32, DDIM / 32), dim3(32, 8)>>>(W1, p_wt, DDIM, FFD);
    splitB_kernel<<<SPLIT_GRID(FFD * DDIM), SPLIT_TB>>>(p_wt, p_bbf, FFD * DDIM, DDIM);
    mma_gemm<<<dim3(FFD / 128, BT / 128), 256, GEMM_SMEM>>>(
        p_abf, p_bbf, b1, nullptr, nullptr, p_abf2, nullptr, nullptr, FFD, 3 * DDIM, 1, 1);

    transpose_kernel<<<dim3(DDIM / 32, FFD / 32), dim3(32, 8)>>>(W2, p_wt, FFD, DDIM);
    splitB_kernel<<<SPLIT_GRID(DDIM * FFD), SPLIT_TB>>>(p_wt, p_bbf, DDIM * FFD, FFD);
    mma_gemm<<<dim3(DDIM / 128, BT / 128), 256, GEMM_SMEM>>>(
        p_abf2, p_bbf, b2, p_x1, out, nullptr, nullptr, nullptr, DDIM, 3 * FFD, 0, 0);
}

// round 11
// speedup vs baseline: 5.9824x; 1.6362x over previous
#include <cuda_runtime.h>
#include <cuda_fp16.h>
#include <cstdint>

#define BB   4
#define TT   2048
#define DDIM 512
#define HH   8
#define DHH  64
#define BT   8192
#define FFD  2048
#define ATT_SCALE 0.044194173824159216f   // 512^-0.5

// ---------------- scratch ----------------
__device__ float g_x1  [(size_t)BT * DDIM];
__device__ float g_wt  [(size_t)FFD * DDIM];        // transposed weight staging (fp32)
__device__ __half g_abf [(size_t)BT * 1024];        // A2-split activations [tok][hi(512)|lo(512)]
__device__ __half g_abf2[(size_t)BT * 4096];        // A2-split ff1 [tok][hi(2048)|lo(2048)]
__device__ __half g_bbf [(size_t)2048 * 2048];      // B2-split weights [N][hi(K)|hi(K)]
__device__ __half g_qs  [(size_t)BT * DDIM];        // q fp16, scaled, [tok][h*64+e]
__device__ __half g_ks  [(size_t)BT * DDIM];        // k fp16
__device__ __half g_vs  [(size_t)BT * 1024];        // v hi|lo [tok][h*128 + part*64 + e]

// ---------------- helpers ----------------
__device__ __forceinline__ uint32_t smem_u32(const void* p) {
    uint32_t a;
    asm("{ .reg .u64 t; cvta.to.shared.u64 t, %1; cvt.u32.u64 %0, t; }" : "=r"(a) : "l"(p));
    return a;
}
__device__ __forceinline__ uint32_t pack_h2(__half a, __half b) {
    return (uint32_t)__half_as_ushort(a) | ((uint32_t)__half_as_ushort(b) << 16);
}

#define LDSM4(d, addr)                                                                  \
    asm volatile("ldmatrix.sync.aligned.m8n8.x4.shared.b16 {%0,%1,%2,%3}, [%4];"        \
                 : "=r"((d)[0]), "=r"((d)[1]), "=r"((d)[2]), "=r"((d)[3]) : "r"(addr))
#define LDSM4T(d, addr)                                                                 \
    asm volatile("ldmatrix.sync.aligned.m8n8.x4.trans.shared.b16 {%0,%1,%2,%3}, [%4];"  \
                 : "=r"((d)[0]), "=r"((d)[1]), "=r"((d)[2]), "=r"((d)[3]) : "r"(addr))

__device__ __forceinline__ void mma16816(float* c, const uint32_t* a,
                                         uint32_t b0, uint32_t b1) {
    asm volatile(
        "mma.sync.aligned.m16n8k16.row.col.f32.f16.f16.f32 "
        "{%0,%1,%2,%3}, {%4,%5,%6,%7}, {%8,%9}, {%0,%1,%2,%3};"
        : "+f"(c[0]), "+f"(c[1]), "+f"(c[2]), "+f"(c[3])
        : "r"(a[0]), "r"(a[1]), "r"(a[2]), "r"(a[3]), "r"(b0), "r"(b1));
}

#define CPASYNC16(dst, src)                                                             \
    asm volatile("cp.async.cg.shared.global [%0], [%1], 16;" :: "r"(dst), "l"(src) : "memory")
#define CPCOMMIT() asm volatile("cp.async.commit_group;" ::: "memory")

// A2 layout pair: hi@off, lo@off+K
__device__ __forceinline__ void splitA2(__half* base, size_t off, int K, float a, float b) {
    __half h0 = __float2half_rn(a), h1 = __float2half_rn(b);
    __half l0 = __float2half_rn(a - __half2float(h0));
    __half l1 = __float2half_rn(b - __half2float(h1));
    *(__half2*)(base + off)     = __halves2half2(h0, h1);
    *(__half2*)(base + off + K) = __halves2half2(l0, l1);
}
// B2 layout pair: hi@off, hi@off+K
__device__ __forceinline__ void splitB2(__half* base, size_t off, int K, float a, float b) {
    __half h0 = __float2half_rn(a), h1 = __float2half_rn(b);
    __half2 hv = __halves2half2(h0, h1);
    *(__half2*)(base + off)     = hv;
    *(__half2*)(base + off + K) = hv;
}

// ---------------- prep kernels ----------------
__global__ void splitB_kernel(const float* __restrict__ in, __half* __restrict__ out,
                              int total, int K) {
    int i = (blockIdx.x * blockDim.x + threadIdx.x) * 4;
    if (i >= total) return;
    int r = i / K, k = i % K;
    float4 v = *(const float4*)(in + i);
    size_t base = (size_t)r * 2 * K + k;
    splitB2(out, base, K, v.x, v.y);
    splitB2(out, base + 2, K, v.z, v.w);
}

__global__ void transpose_kernel(const float* __restrict__ in, float* __restrict__ out,
                                 int K, int N) {
    __shared__ float t[32][33];
    int n0 = blockIdx.x * 32, k0 = blockIdx.y * 32;
    int x = threadIdx.x, y = threadIdx.y;
    #pragma unroll
    for (int r = y; r < 32; r += 8)
        t[r][x] = in[(size_t)(k0 + r) * N + n0 + x];
    __syncthreads();
    #pragma unroll
    for (int r = y; r < 32; r += 8)
        out[(size_t)(n0 + r) * K + k0 + x] = t[x][r];
}

__global__ void repack_qkvT_kernel(const float* __restrict__ Wq, const float* __restrict__ Wk,
                                   const float* __restrict__ Wv, float* __restrict__ out) {
    int idx = blockIdx.x * blockDim.x + threadIdx.x;
    if (idx >= 1536 * DDIM) return;
    int n = idx / DDIM, d = idx % DDIM;
    int which = n / DDIM;
    int col = n % DDIM;
    int h = col / DHH, e = col % DHH;
    const float* W = (which == 0) ? Wq : (which == 1) ? Wk : Wv;
    out[idx] = W[((size_t)h * DDIM + d) * DHH + e];
}

// ---------------- LayerNorm fused with A2-split ----------------
__global__ __launch_bounds__(128) void ln_split_kernel(const float* __restrict__ x,
                                                       const float* __restrict__ g,
                                                       const float* __restrict__ b,
                                                       __half* __restrict__ out) {
    int row = blockIdx.x;
    int t = threadIdx.x;
    const float4* xr = (const float4*)(x + (size_t)row * DDIM);
    float4 v = xr[t];
    float s = v.x + v.y + v.z + v.w;
    float q = v.x * v.x + v.y * v.y + v.z * v.z + v.w * v.w;
    #pragma unroll
    for (int off = 16; off; off >>= 1) {
        s += __shfl_xor_sync(0xffffffffu, s, off);
        q += __shfl_xor_sync(0xffffffffu, q, off);
    }
    __shared__ float ss[4], qs[4];
    if ((t & 31) == 0) { ss[t >> 5] = s; qs[t >> 5] = q; }
    __syncthreads();
    s = ss[0] + ss[1] + ss[2] + ss[3];
    q = qs[0] + qs[1] + qs[2] + qs[3];
    float mean = s * (1.0f / DDIM);
    float var  = q * (1.0f / DDIM) - mean * mean;
    float inv  = rsqrtf(var + 1e-5f);
    float4 gv = ((const float4*)g)[t];
    float4 bv = ((const float4*)b)[t];
    float o0 = (v.x - mean) * inv * gv.x + bv.x;
    float o1 = (v.y - mean) * inv * gv.y + bv.y;
    float o2 = (v.z - mean) * inv * gv.z + bv.z;
    float o3 = (v.w - mean) * inv * gv.w + bv.w;
    size_t base = (size_t)row * 1024 + t * 4;
    splitA2(out, base, DDIM, o0, o1);
    splitA2(out, base + 2, DDIM, o2, o3);
}

// ---------------- HMMA fp16 GEMM, 3-stage cp.async pipeline ----------------
// mode 0: fp32 C (+bias/relu/res).  mode 1: Cs = A2-split [M][2N].  mode 2: qkv outputs.
#define GEMM_SMEM (3 * 32768)

__global__ __launch_bounds__(256) void mma_gemm(const __half* __restrict__ A,
                                                const __half* __restrict__ B,
                                                const float* __restrict__ bias,
                                                const float* __restrict__ res,
                                                float* __restrict__ C,
                                                __half* __restrict__ Cs,
                                                __half* __restrict__ Ko,
                                                __half* __restrict__ Vo,
                                                int N, int K2, int relu, int mode) {
    extern __shared__ __align__(1024) char smem[];
    const uint32_t sb = smem_u32(smem);
    const int tid = threadIdx.x;
    const int wid = tid >> 5, lane = tid & 31;
    const int brow = blockIdx.y << 7, bcol = blockIdx.x << 7;

    const int nchunk = K2 >> 6;
    const int lrow = tid >> 1;
    const int lseg = (tid & 1) << 5;
    const __half* Ap = A + (size_t)(brow + lrow) * K2 + lseg;
    const __half* Bp = B + (size_t)(bcol + lrow) * K2 + lseg;
    const uint32_t so = lrow * 128 + (lseg << 1);
    uint32_t sw_off[4];
    #pragma unroll
    for (int u = 0; u < 4; u++) {
        uint32_t bo = so + (u << 4);
        sw_off[u] = bo ^ ((bo >> 3) & 0x70);
    }

    const int wm = (wid & 3) << 5;
    const int wn = (wid >> 2) << 6;
    const int a_roff = lane & 15;
    const int a_cext = (lane & 16) ? 16 : 0;
    const int b_roff = (lane & 7) + ((lane & 16) ? 8 : 0);
    const int b_cext = (lane & 8) ? 16 : 0;

    auto issue_chunk = [&](int cc) {
        const uint32_t da = sb + (uint32_t)(cc % 3) * 32768u;
        const char* ag = (const char*)(Ap + ((size_t)cc << 6));
        const char* bg = (const char*)(Bp + ((size_t)cc << 6));
        #pragma unroll
        for (int u = 0; u < 4; u++) {
            CPASYNC16(da + sw_off[u], ag + u * 16);
            CPASYNC16(da + 16384 + sw_off[u], bg + u * 16);
        }
        CPCOMMIT();
    };

    float acc[2][8][4];
    #pragma unroll
    for (int mi = 0; mi < 2; mi++)
        #pragma unroll
        for (int nj = 0; nj < 8; nj++)
            #pragma unroll
            for (int u = 0; u < 4; u++) acc[mi][nj][u] = 0.0f;

    issue_chunk(0);
    issue_chunk(1);

    for (int c = 0; c < nchunk; c++) {
        if (c + 1 < nchunk) asm volatile("cp.async.wait_group 1;" ::: "memory");
        else                asm volatile("cp.async.wait_group 0;" ::: "memory");
        __syncthreads();
        if (c + 2 < nchunk) issue_chunk(c + 2);

        const uint32_t sa = sb + (uint32_t)(c % 3) * 32768u;
        const uint32_t sB = sa + 16384;
        #pragma unroll
        for (int k = 0; k < 4; k++) {
            const int cb0 = k << 5;
            uint32_t afr[2][4];
            #pragma unroll
            for (int mi = 0; mi < 2; mi++) {
                int row = wm + (mi << 4) + a_roff;
                LDSM4(afr[mi], sa + row * 128 + ((cb0 + a_cext) ^ ((row & 7) << 4)));
            }
            uint32_t bfr[4][4];
            #pragma unroll
            for (int g = 0; g < 4; g++) {
                int row = wn + (g << 4) + b_roff;
                LDSM4(bfr[g], sB + row * 128 + ((cb0 + b_cext) ^ ((row & 7) << 4)));
            }
            #pragma unroll
            for (int mi = 0; mi < 2; mi++)
                #pragma unroll
                for (int nj = 0; nj < 8; nj++)
                    mma16816(acc[mi][nj], afr[mi],
                             bfr[nj >> 1][(nj & 1) << 1], bfr[nj >> 1][((nj & 1) << 1) + 1]);
        }
    }

    // ---------------- epilogue ----------------
    const int qr = lane >> 2;
    const int qc = (lane & 3) << 1;
    #pragma unroll
    for (int mi = 0; mi < 2; mi++) {
        #pragma unroll
        for (int half = 0; half < 2; half++) {
            const int m = brow + wm + (mi << 4) + qr + (half << 3);
            #pragma unroll
            for (int nj = 0; nj < 8; nj++) {
                const int col = bcol + wn + (nj << 3) + qc;
                float v0 = acc[mi][nj][half * 2 + 0];
                float v1 = acc[mi][nj][half * 2 + 1];
                if (bias) {
                    float2 bb = *(const float2*)(bias + col);
                    v0 += bb.x; v1 += bb.y;
                }
                if (relu) { v0 = fmaxf(v0, 0.0f); v1 = fmaxf(v1, 0.0f); }
                if (res) {
                    float2 rr = *(const float2*)(res + (size_t)m * N + col);
                    v0 += rr.x; v1 += rr.y;
                }
                if (mode == 0) {
                    *(float2*)(C + (size_t)m * N + col) = make_float2(v0, v1);
                } else if (mode == 1) {
                    splitA2(Cs, (size_t)m * 2 * N + col, N, v0, v1);
                } else {
                    if (col < 512) {          // q: scaled single fp16
                        *(__half2*)(Ko + (size_t)m * 512 + col) =
                            __halves2half2(__float2half_rn(v0 * ATT_SCALE),
                                           __float2half_rn(v1 * ATT_SCALE));
                    } else if (col < 1024) {  // k: single fp16
                        *(__half2*)(Cs + (size_t)m * 512 + (col - 512)) =
                            __halves2half2(__float2half_rn(v0), __float2half_rn(v1));
                    } else {                  // v: hi|lo
                        int cc = col - 1024;
                        int hh = cc >> 6, e = cc & 63;
                        size_t off = (size_t)m * 1024 + hh * 128 + e;
                        __half h0 = __float2half_rn(v0), h1 = __float2half_rn(v1);
                        __half l0 = __float2half_rn(v0 - __half2float(h0));
                        __half l1 = __float2half_rn(v1 - __half2float(h1));
                        *(__half2*)(Vo + off)      = __halves2half2(h0, h1);
                        *(__half2*)(Vo + off + 64) = __halves2half2(l0, l1);
                    }
                }
            }
        }
    }
}

// ---------------- mma flash attention (fp16, register P/Q, cp.async K/V) ----------------
// smem: Qs[64][64] | Ks[64][64] (swizzled 128B rows) | Vs 2 x [128][72]
#define ATT_SMEM 53248
#define V_STRIDE  144   // bytes per row (72 fp16)
#define V_BUF     18432 // 128 * 144

__global__ __launch_bounds__(128) void attn_mma(const __half* __restrict__ qsg,
                                                const __half* __restrict__ ksg,
                                                const __half* __restrict__ vsg,
                                                __half* __restrict__ o_split) {
    extern __shared__ __align__(16) char smc[];
    const uint32_t Q0 = smem_u32(smc);
    const uint32_t K0 = Q0 + 8192;
    const uint32_t V0 = Q0 + 16384;

    const int it = gridDim.x - 1 - blockIdx.x;   // big tiles first
    const int h = blockIdx.y, b = blockIdx.z;
    const int qbase = it * 64;
    const int tid = threadIdx.x;
    const int wq = tid >> 5;
    const int lane = tid & 31;

    auto issue_K = [&](int jt2) {
        int row = tid >> 1, halfr = tid & 1;
        const char* src = (const char*)(ksg + (size_t)(b * TT + jt2 * 64 + row) * 512 + h * 64 + halfr * 32);
        #pragma unroll
        for (int u = 0; u < 4; u++) {
            uint32_t colb = halfr * 64 + u * 16;
            CPASYNC16(K0 + row * 128 + (colb ^ ((row & 7) << 4)), src + u * 16);
        }
        CPCOMMIT();
    };
    auto issue_V = [&](int jt2) {
        int key = tid & 63, part = tid >> 6;
        const char* src = (const char*)(vsg + (size_t)(b * TT + jt2 * 64 + key) * 1024 + h * 128 + part * 64);
        uint32_t dst = V0 + (uint32_t)(jt2 & 1) * V_BUF + tid * V_STRIDE;
        #pragma unroll
        for (int u = 0; u < 8; u++) CPASYNC16(dst + u * 16, src + u * 16);
        CPCOMMIT();
    };

    issue_K(0);
    issue_V(0);

    // Q tile (scaled fp16) -> smem, then preload fragments to registers
    {
        int row = tid >> 1, halfr = tid & 1;
        const uint4* src = (const uint4*)(qsg + (size_t)(b * TT + qbase + row) * 512 + h * 64 + halfr * 32);
        #pragma unroll
        for (int u = 0; u < 4; u++) {
            uint4 v = src[u];
            uint32_t colb = halfr * 64 + u * 16;
            asm volatile("st.shared.v4.b32 [%0], {%1,%2,%3,%4};"
                         :: "r"(Q0 + row * 128 + (colb ^ ((row & 7) << 4))),
                            "r"(v.x), "r"(v.y), "r"(v.z), "r"(v.w) : "memory");
        }
    }
    __syncthreads();

    const int a_roff = lane & 15;
    const int a_cext = (lane & 16) ? 16 : 0;
    const int b_roff = (lane & 7) + ((lane & 16) ? 8 : 0);
    const int b_cext = (lane & 8) ? 16 : 0;
    const int v_cext = (lane & 16) ? 16 : 0;

    uint32_t qf[4][4];
    #pragma unroll
    for (int ks = 0; ks < 4; ks++) {
        int row = wq * 16 + a_roff;
        LDSM4(qf[ks], Q0 + row * 128 + (((ks << 5) + a_cext) ^ ((row & 7) << 4)));
    }

    float acco[8][4];
    #pragma unroll
    for (int t = 0; t < 8; t++)
        #pragma unroll
        for (int u = 0; u < 4; u++) acco[t][u] = 0.0f;
    float m0 = -1e30f, m1 = -1e30f, l0 = 0.0f, l1 = 0.0f;
    const int r0 = lane >> 2;
    const int qlr0 = wq * 16 + r0;
    const int qlr1 = qlr0 + 8;

    for (int jt = 0; jt <= it; jt++) {
        asm volatile("cp.async.wait_group 1;" ::: "memory");   // K(jt) done
        __syncthreads();

        // S = Q @ K^T  (m16 per warp, n64, k64)
        float accs[8][4];
        #pragma unroll
        for (int t = 0; t < 8; t++)
            #pragma unroll
            for (int u = 0; u < 4; u++) accs[t][u] = 0.0f;
        #pragma unroll
        for (int ks = 0; ks < 4; ks++) {
            uint32_t bf[4][4];
            #pragma unroll
            for (int g = 0; g < 4; g++) {
                int row = g * 16 + b_roff;
                LDSM4(bf[g], K0 + row * 128 + (((ks << 5) + b_cext) ^ ((row & 7) << 4)));
            }
            #pragma unroll
            for (int nj = 0; nj < 8; nj++)
                mma16816(accs[nj], qf[ks],
                         bf[nj >> 1][(nj & 1) << 1], bf[nj >> 1][((nj & 1) << 1) + 1]);
        }
        __syncthreads();   // all warps done reading K(jt)
        if (jt < it) { issue_K(jt + 1); issue_V(jt + 1); }

        // softmax (register-resident)
        if (jt == it) {
            #pragma unroll
            for (int t = 0; t < 8; t++) {
                int c0 = t * 8 + (lane & 3) * 2;
                if (c0     > qlr0) accs[t][0] = -1e30f;
                if (c0 + 1 > qlr0) accs[t][1] = -1e30f;
                if (c0     > qlr1) accs[t][2] = -1e30f;
                if (c0 + 1 > qlr1) accs[t][3] = -1e30f;
            }
        }
        float mx0 = -1e30f, mx1 = -1e30f;
        #pragma unroll
        for (int t = 0; t < 8; t++) {
            mx0 = fmaxf(mx0, fmaxf(accs[t][0], accs[t][1]));
            mx1 = fmaxf(mx1, fmaxf(accs[t][2], accs[t][3]));
        }
        mx0 = fmaxf(mx0, __shfl_xor_sync(0xffffffffu, mx0, 1));
        mx0 = fmaxf(mx0, __shfl_xor_sync(0xffffffffu, mx0, 2));
        mx1 = fmaxf(mx1, __shfl_xor_sync(0xffffffffu, mx1, 1));
        mx1 = fmaxf(mx1, __shfl_xor_sync(0xffffffffu, mx1, 2));
        float nm0 = fmaxf(m0, mx0), nm1 = fmaxf(m1, mx1);
        float al0 = __expf(m0 - nm0), al1 = __expf(m1 - nm1);
        float s0 = 0.0f, s1 = 0.0f;
        #pragma unroll
        for (int t = 0; t < 8; t++) {
            accs[t][0] = __expf(accs[t][0] - nm0);
            accs[t][1] = __expf(accs[t][1] - nm0);
            accs[t][2] = __expf(accs[t][2] - nm1);
            accs[t][3] = __expf(accs[t][3] - nm1);
            s0 += accs[t][0] + accs[t][1];
            s1 += accs[t][2] + accs[t][3];
        }
        s0 += __shfl_xor_sync(0xffffffffu, s0, 1);
        s0 += __shfl_xor_sync(0xffffffffu, s0, 2);
        s1 += __shfl_xor_sync(0xffffffffu, s1, 1);
        s1 += __shfl_xor_sync(0xffffffffu, s1, 2);
        l0 = l0 * al0 + s0;
        l1 = l1 * al1 + s1;
        m0 = nm0; m1 = nm1;
        #pragma unroll
        for (int t = 0; t < 8; t++) {
            acco[t][0] *= al0; acco[t][1] *= al0;
            acco[t][2] *= al1; acco[t][3] *= al1;
        }

        if (jt < it) asm volatile("cp.async.wait_group 2;" ::: "memory");   // V(jt) done
        else         asm volatile("cp.async.wait_group 0;" ::: "memory");
        __syncthreads();

        // O += P@Vhi + P@Vlo  (P single fp16, register fragments)
        const uint32_t vb = V0 + (uint32_t)(jt & 1) * V_BUF;
        #pragma unroll
        for (int t = 0; t < 4; t++) {
            uint32_t af[4];
            af[0] = pack_h2(__float2half_rn(accs[2*t][0]),   __float2half_rn(accs[2*t][1]));
            af[1] = pack_h2(__float2half_rn(accs[2*t][2]),   __float2half_rn(accs[2*t][3]));
            af[2] = pack_h2(__float2half_rn(accs[2*t+1][0]), __float2half_rn(accs[2*t+1][1]));
            af[3] = pack_h2(__float2half_rn(accs[2*t+1][2]), __float2half_rn(accs[2*t+1][3]));
            uint32_t bh[4][4], bl[4][4];
            #pragma unroll
            for (int g = 0; g < 4; g++) {
                int rhi = t * 16 + (lane & 15);
                LDSM4T(bh[g], vb + rhi * V_STRIDE + g * 32 + v_cext);
                LDSM4T(bl[g], vb + (64 + rhi) * V_STRIDE + g * 32 + v_cext);
            }
            #pragma unroll
            for (int nj = 0; nj < 8; nj++) {
                mma16816(acco[nj], af, bh[nj >> 1][(nj & 1) << 1], bh[nj >> 1][((nj & 1) << 1) + 1]);
                mma16816(acco[nj], af, bl[nj >> 1][(nj & 1) << 1], bl[nj >> 1][((nj & 1) << 1) + 1]);
            }
        }
    }

    // epilogue: divide by l, write A2-split o into o_split [tok][1024]
    const float i0 = 1.0f / l0, i1 = 1.0f / l1;
    const int gr0 = b * TT + qbase + qlr0;
    const int gr1 = b * TT + qbase + qlr1;
    #pragma unroll
    for (int t = 0; t < 8; t++) {
        int e = t * 8 + (lane & 3) * 2;
        splitA2(o_split, (size_t)gr0 * 1024 + h * 64 + e, DDIM,
                acco[t][0] * i0, acco[t][1] * i0);
        splitA2(o_split, (size_t)gr1 * 1024 + h * 64 + e, DDIM,
                acco[t][2] * i1, acco[t][3] * i1);
    }
}

// ---------------- launch ----------------
extern "C" void kernel_launch(void* const* d_in, const int* in_sizes, int n_in,
                              void* d_out, int out_size) {
    const float* x     = (const float*)d_in[0];
    const float* ln1_g = (const float*)d_in[1];
    const float* ln1_b = (const float*)d_in[2];
    const float* Wq    = (const float*)d_in[3];
    const float* Wk    = (const float*)d_in[4];
    const float* Wv    = (const float*)d_in[5];
    const float* Wproj = (const float*)d_in[6];
    const float* bproj = (const float*)d_in[7];
    const float* W1    = (const float*)d_in[8];
    const float* b1    = (const float*)d_in[9];
    const float* W2    = (const float*)d_in[10];
    const float* b2    = (const float*)d_in[11];
    float* out = (float*)d_out;

    float *p_x1, *p_wt;
    __half *p_abf, *p_abf2, *p_bbf, *p_qs, *p_ks, *p_vs;
    cudaGetSymbolAddress((void**)&p_x1,   g_x1);
    cudaGetSymbolAddress((void**)&p_wt,   g_wt);
    cudaGetSymbolAddress((void**)&p_abf,  g_abf);
    cudaGetSymbolAddress((void**)&p_abf2, g_abf2);
    cudaGetSymbolAddress((void**)&p_bbf,  g_bbf);
    cudaGetSymbolAddress((void**)&p_qs,   g_qs);
    cudaGetSymbolAddress((void**)&p_ks,   g_ks);
    cudaGetSymbolAddress((void**)&p_vs,   g_vs);

    cudaFuncSetAttribute(attn_mma, cudaFuncAttributeMaxDynamicSharedMemorySize, ATT_SMEM);
    cudaFuncSetAttribute(mma_gemm, cudaFuncAttributeMaxDynamicSharedMemorySize, GEMM_SMEM);

    const int SPLIT_TB = 256;
    #define SPLIT_GRID(n) (((n) / 4 + SPLIT_TB - 1) / SPLIT_TB)

    // ---- attention sublayer ----
    ln_split_kernel<<<BT, 128>>>(x, ln1_g, ln1_b, p_abf);
    repack_qkvT_kernel<<<(1536 * DDIM + 255) / 256, 256>>>(Wq, Wk, Wv, p_wt);
    splitB_kernel<<<SPLIT_GRID(1536 * DDIM), SPLIT_TB>>>(p_wt, p_bbf, 1536 * DDIM, DDIM);
    // mode 2: Ko<-q(scaled), Cs<-k, Vo<-v   (note: q->Ko=g_qs, k->Cs=g_ks)
    mma_gemm<<<dim3(1536 / 128, BT / 128), 256, GEMM_SMEM>>>(
        p_abf, p_bbf, nullptr, nullptr, nullptr, p_ks, p_qs, p_vs, 1536, 1024, 0, 2);
    attn_mma<<<dim3(TT / 64, HH, BB), 128, ATT_SMEM>>>(p_qs, p_ks, p_vs, p_abf);

    transpose_kernel<<<dim3(DDIM / 32, DDIM / 32), dim3(32, 8)>>>(Wproj, p_wt, DDIM, DDIM);
    splitB_kernel<<<SPLIT_GRID(DDIM * DDIM), SPLIT_TB>>>(p_wt, p_bbf, DDIM * DDIM, DDIM);
    mma_gemm<<<dim3(DDIM / 128, BT / 128), 256, GEMM_SMEM>>>(
        p_abf, p_bbf, bproj, x, p_x1, nullptr, nullptr, nullptr, DDIM, 1024, 0, 0);

    // ---- FFN sublayer ----
    ln_split_kernel<<<BT, 128>>>(p_x1, ln1_g, ln1_b, p_abf);
    transpose_kernel<<<dim3(FFD / 32, DDIM / 32), dim3(32, 8)>>>(W1, p_wt, DDIM, FFD);
    splitB_kernel<<<SPLIT_GRID(FFD * DDIM), SPLIT_TB>>>(p_wt, p_bbf, FFD * DDIM, DDIM);
    mma_gemm<<<dim3(FFD / 128, BT / 128), 256, GEMM_SMEM>>>(
        p_abf, p_bbf, b1, nullptr, nullptr, p_abf2, nullptr, nullptr, FFD, 1024, 1, 1);

    transpose_kernel<<<dim3(DDIM / 32, FFD / 32), dim3(32, 8)>>>(W2, p_wt, FFD, DDIM);
    splitB_kernel<<<SPLIT_GRID(DDIM * FFD), SPLIT_TB>>>(p_wt, p_bbf, DDIM * FFD, FFD);
    mma_gemm<<<dim3(DDIM / 128, BT / 128), 256, GEMM_SMEM>>>(
        p_abf2, p_bbf, b2, p_x1, out, nullptr, nullptr, nullptr, DDIM, 4096, 0, 0);
}

// round 12
// speedup vs baseline: 10.6382x; 1.7783x over previous
#include <cuda_runtime.h>
#include <cuda_fp16.h>
#include <cstdint>

#define BB   4
#define TT   2048
#define DDIM 512
#define HH   8
#define DHH  64
#define BT   8192
#define FFD  2048
#define ATT_SCALE 0.044194173824159216f   // 512^-0.5

// ---------------- scratch ----------------
__device__ float g_x1  [(size_t)BT * DDIM];
__device__ __half g_abf [(size_t)BT * DDIM];        // fp16 activations [tok][512]
__device__ __half g_abf2[(size_t)BT * FFD];         // fp16 ff1 [tok][2048]
__device__ __half g_bbf [(size_t)2048 * 2048];      // fp16 weights [N][K] (transposed)
__device__ __half g_qs  [(size_t)BT * DDIM];        // q fp16, scaled, [tok][h*64+e]
__device__ __half g_ks  [(size_t)BT * DDIM];        // k fp16
__device__ __half g_vs  [(size_t)BT * DDIM];        // v fp16

// ---------------- helpers ----------------
__device__ __forceinline__ uint32_t smem_u32(const void* p) {
    uint32_t a;
    asm("{ .reg .u64 t; cvta.to.shared.u64 t, %1; cvt.u32.u64 %0, t; }" : "=r"(a) : "l"(p));
    return a;
}
__device__ __forceinline__ uint32_t pack_h2(__half a, __half b) {
    return (uint32_t)__half_as_ushort(a) | ((uint32_t)__half_as_ushort(b) << 16);
}

#define LDSM4(d, addr)                                                                  \
    asm volatile("ldmatrix.sync.aligned.m8n8.x4.shared.b16 {%0,%1,%2,%3}, [%4];"        \
                 : "=r"((d)[0]), "=r"((d)[1]), "=r"((d)[2]), "=r"((d)[3]) : "r"(addr))
#define LDSM4T(d, addr)                                                                 \
    asm volatile("ldmatrix.sync.aligned.m8n8.x4.trans.shared.b16 {%0,%1,%2,%3}, [%4];"  \
                 : "=r"((d)[0]), "=r"((d)[1]), "=r"((d)[2]), "=r"((d)[3]) : "r"(addr))

__device__ __forceinline__ void mma16816(float* c, const uint32_t* a,
                                         uint32_t b0, uint32_t b1) {
    asm volatile(
        "mma.sync.aligned.m16n8k16.row.col.f32.f16.f16.f32 "
        "{%0,%1,%2,%3}, {%4,%5,%6,%7}, {%8,%9}, {%0,%1,%2,%3};"
        : "+f"(c[0]), "+f"(c[1]), "+f"(c[2]), "+f"(c[3])
        : "r"(a[0]), "r"(a[1]), "r"(a[2]), "r"(a[3]), "r"(b0), "r"(b1));
}

#define CPASYNC16(dst, src)                                                             \
    asm volatile("cp.async.cg.shared.global [%0], [%1], 16;" :: "r"(dst), "l"(src) : "memory")
#define CPCOMMIT() asm volatile("cp.async.commit_group;" ::: "memory")

// ---------------- prep kernels ----------------
// fp32 [K,N] -> fp16 [N,K]
__global__ void transposeh_kernel(const float* __restrict__ in, __half* __restrict__ out,
                                  int K, int N) {
    __shared__ float t[32][33];
    int n0 = blockIdx.x * 32, k0 = blockIdx.y * 32;
    int x = threadIdx.x, y = threadIdx.y;
    #pragma unroll
    for (int r = y; r < 32; r += 8)
        t[r][x] = in[(size_t)(k0 + r) * N + n0 + x];
    __syncthreads();
    #pragma unroll
    for (int r = y; r < 32; r += 8)
        out[(size_t)(n0 + r) * K + k0 + x] = __float2half_rn(t[x][r]);
}

// Wq/Wk/Wv (H,D,DH) -> fp16 [1536][512] transposed ([n][d])
__global__ void repack_qkvTh_kernel(const float* __restrict__ Wq, const float* __restrict__ Wk,
                                    const float* __restrict__ Wv, __half* __restrict__ out) {
    int idx = blockIdx.x * blockDim.x + threadIdx.x;
    if (idx >= 1536 * DDIM) return;
    int n = idx / DDIM, d = idx % DDIM;
    int which = n / DDIM;
    int col = n % DDIM;
    int h = col / DHH, e = col % DHH;
    const float* W = (which == 0) ? Wq : (which == 1) ? Wk : Wv;
    out[idx] = __float2half_rn(W[((size_t)h * DDIM + d) * DHH + e]);
}

// ---------------- LayerNorm -> fp16 ----------------
__global__ __launch_bounds__(128) void ln_h_kernel(const float* __restrict__ x,
                                                   const float* __restrict__ g,
                                                   const float* __restrict__ b,
                                                   __half* __restrict__ out) {
    int row = blockIdx.x;
    int t = threadIdx.x;
    const float4* xr = (const float4*)(x + (size_t)row * DDIM);
    float4 v = xr[t];
    float s = v.x + v.y + v.z + v.w;
    float q = v.x * v.x + v.y * v.y + v.z * v.z + v.w * v.w;
    #pragma unroll
    for (int off = 16; off; off >>= 1) {
        s += __shfl_xor_sync(0xffffffffu, s, off);
        q += __shfl_xor_sync(0xffffffffu, q, off);
    }
    __shared__ float ss[4], qs[4];
    if ((t & 31) == 0) { ss[t >> 5] = s; qs[t >> 5] = q; }
    __syncthreads();
    s = ss[0] + ss[1] + ss[2] + ss[3];
    q = qs[0] + qs[1] + qs[2] + qs[3];
    float mean = s * (1.0f / DDIM);
    float var  = q * (1.0f / DDIM) - mean * mean;
    float inv  = rsqrtf(var + 1e-5f);
    float4 gv = ((const float4*)g)[t];
    float4 bv = ((const float4*)b)[t];
    float o0 = (v.x - mean) * inv * gv.x + bv.x;
    float o1 = (v.y - mean) * inv * gv.y + bv.y;
    float o2 = (v.z - mean) * inv * gv.z + bv.z;
    float o3 = (v.w - mean) * inv * gv.w + bv.w;
    __half2* op = (__half2*)(out + (size_t)row * DDIM + t * 4);
    op[0] = __halves2half2(__float2half_rn(o0), __float2half_rn(o1));
    op[1] = __halves2half2(__float2half_rn(o2), __float2half_rn(o3));
}

// ---------------- HMMA fp16 GEMM, 3-stage cp.async pipeline ----------------
// mode 0: fp32 C (+bias/relu/res).  mode 1: Cs = fp16 [M][N].  mode 2: q/k/v outputs.
#define GEMM_SMEM (3 * 32768)

__global__ __launch_bounds__(256) void mma_gemm(const __half* __restrict__ A,
                                                const __half* __restrict__ B,
                                                const float* __restrict__ bias,
                                                const float* __restrict__ res,
                                                float* __restrict__ C,
                                                __half* __restrict__ Cs,
                                                __half* __restrict__ Ko,
                                                __half* __restrict__ Vo,
                                                int N, int K, int relu, int mode) {
    extern __shared__ __align__(1024) char smem[];
    const uint32_t sb = smem_u32(smem);
    const int tid = threadIdx.x;
    const int wid = tid >> 5, lane = tid & 31;
    const int brow = blockIdx.y << 7, bcol = blockIdx.x << 7;

    const int nchunk = K >> 6;
    const int lrow = tid >> 1;
    const int lseg = (tid & 1) << 5;
    const __half* Ap = A + (size_t)(brow + lrow) * K + lseg;
    const __half* Bp = B + (size_t)(bcol + lrow) * K + lseg;
    const uint32_t so = lrow * 128 + (lseg << 1);
    uint32_t sw_off[4];
    #pragma unroll
    for (int u = 0; u < 4; u++) {
        uint32_t bo = so + (u << 4);
        sw_off[u] = bo ^ ((bo >> 3) & 0x70);
    }

    const int wm = (wid & 3) << 5;
    const int wn = (wid >> 2) << 6;
    const int a_roff = lane & 15;
    const int a_cext = (lane & 16) ? 16 : 0;
    const int b_roff = (lane & 7) + ((lane & 16) ? 8 : 0);
    const int b_cext = (lane & 8) ? 16 : 0;

    auto issue_chunk = [&](int cc) {
        const uint32_t da = sb + (uint32_t)(cc % 3) * 32768u;
        const char* ag = (const char*)(Ap + ((size_t)cc << 6));
        const char* bg = (const char*)(Bp + ((size_t)cc << 6));
        #pragma unroll
        for (int u = 0; u < 4; u++) {
            CPASYNC16(da + sw_off[u], ag + u * 16);
            CPASYNC16(da + 16384 + sw_off[u], bg + u * 16);
        }
        CPCOMMIT();
    };

    float acc[2][8][4];
    #pragma unroll
    for (int mi = 0; mi < 2; mi++)
        #pragma unroll
        for (int nj = 0; nj < 8; nj++)
            #pragma unroll
            for (int u = 0; u < 4; u++) acc[mi][nj][u] = 0.0f;

    issue_chunk(0);
    issue_chunk(1);

    for (int c = 0; c < nchunk; c++) {
        if (c + 1 < nchunk) asm volatile("cp.async.wait_group 1;" ::: "memory");
        else                asm volatile("cp.async.wait_group 0;" ::: "memory");
        __syncthreads();
        if (c + 2 < nchunk) issue_chunk(c + 2);

        const uint32_t sa = sb + (uint32_t)(c % 3) * 32768u;
        const uint32_t sB = sa + 16384;
        #pragma unroll
        for (int k = 0; k < 4; k++) {
            const int cb0 = k << 5;
            uint32_t afr[2][4];
            #pragma unroll
            for (int mi = 0; mi < 2; mi++) {
                int row = wm + (mi << 4) + a_roff;
                LDSM4(afr[mi], sa + row * 128 + ((cb0 + a_cext) ^ ((row & 7) << 4)));
            }
            uint32_t bfr[4][4];
            #pragma unroll
            for (int g = 0; g < 4; g++) {
                int row = wn + (g << 4) + b_roff;
                LDSM4(bfr[g], sB + row * 128 + ((cb0 + b_cext) ^ ((row & 7) << 4)));
            }
            #pragma unroll
            for (int mi = 0; mi < 2; mi++)
                #pragma unroll
                for (int nj = 0; nj < 8; nj++)
                    mma16816(acc[mi][nj], afr[mi],
                             bfr[nj >> 1][(nj & 1) << 1], bfr[nj >> 1][((nj & 1) << 1) + 1]);
        }
    }

    // ---------------- epilogue ----------------
    const int qr = lane >> 2;
    const int qc = (lane & 3) << 1;
    #pragma unroll
    for (int mi = 0; mi < 2; mi++) {
        #pragma unroll
        for (int half = 0; half < 2; half++) {
            const int m = brow + wm + (mi << 4) + qr + (half << 3);
            #pragma unroll
            for (int nj = 0; nj < 8; nj++) {
                const int col = bcol + wn + (nj << 3) + qc;
                float v0 = acc[mi][nj][half * 2 + 0];
                float v1 = acc[mi][nj][half * 2 + 1];
                if (bias) {
                    float2 bb = *(const float2*)(bias + col);
                    v0 += bb.x; v1 += bb.y;
                }
                if (relu) { v0 = fmaxf(v0, 0.0f); v1 = fmaxf(v1, 0.0f); }
                if (res) {
                    float2 rr = *(const float2*)(res + (size_t)m * N + col);
                    v0 += rr.x; v1 += rr.y;
                }
                if (mode == 0) {
                    *(float2*)(C + (size_t)m * N + col) = make_float2(v0, v1);
                } else if (mode == 1) {
                    *(__half2*)(Cs + (size_t)m * N + col) =
                        __halves2half2(__float2half_rn(v0), __float2half_rn(v1));
                } else {
                    if (col < 512) {          // q: scaled fp16
                        *(__half2*)(Ko + (size_t)m * 512 + col) =
                            __halves2half2(__float2half_rn(v0 * ATT_SCALE),
                                           __float2half_rn(v1 * ATT_SCALE));
                    } else if (col < 1024) {  // k
                        *(__half2*)(Cs + (size_t)m * 512 + (col - 512)) =
                            __halves2half2(__float2half_rn(v0), __float2half_rn(v1));
                    } else {                  // v
                        *(__half2*)(Vo + (size_t)m * 512 + (col - 1024)) =
                            __halves2half2(__float2half_rn(v0), __float2half_rn(v1));
                    }
                }
            }
        }
    }
}

// ---------------- mma flash attention (all fp16 single-pass) ----------------
// smem: Qs[64][64] | Ks[64][64] | Vs 2 x [64][64]  (all 128B swizzled rows)
#define ATT_SMEM 32768
#define V_BUF 8192

__global__ __launch_bounds__(128) void attn_mma(const __half* __restrict__ qsg,
                                                const __half* __restrict__ ksg,
                                                const __half* __restrict__ vsg,
                                                __half* __restrict__ o_out) {
    extern __shared__ __align__(16) char smc[];
    const uint32_t Q0 = smem_u32(smc);
    const uint32_t K0 = Q0 + 8192;
    const uint32_t V0 = Q0 + 16384;

    const int it = gridDim.x - 1 - blockIdx.x;   // big tiles first
    const int h = blockIdx.y, b = blockIdx.z;
    const int qbase = it * 64;
    const int tid = threadIdx.x;
    const int wq = tid >> 5;
    const int lane = tid & 31;

    auto issue_K = [&](int jt2) {
        int row = tid >> 1, halfr = tid & 1;
        const char* src = (const char*)(ksg + (size_t)(b * TT + jt2 * 64 + row) * 512 + h * 64 + halfr * 32);
        #pragma unroll
        for (int u = 0; u < 4; u++) {
            uint32_t colb = halfr * 64 + u * 16;
            CPASYNC16(K0 + row * 128 + (colb ^ ((row & 7) << 4)), src + u * 16);
        }
        CPCOMMIT();
    };
    auto issue_V = [&](int jt2) {
        int row = tid >> 1, halfr = tid & 1;
        const char* src = (const char*)(vsg + (size_t)(b * TT + jt2 * 64 + row) * 512 + h * 64 + halfr * 32);
        uint32_t vb = V0 + (uint32_t)(jt2 & 1) * V_BUF;
        #pragma unroll
        for (int u = 0; u < 4; u++) {
            uint32_t colb = halfr * 64 + u * 16;
            CPASYNC16(vb + row * 128 + (colb ^ ((row & 7) << 4)), src + u * 16);
        }
        CPCOMMIT();
    };

    issue_K(0);
    issue_V(0);

    // Q tile (scaled fp16) -> smem, then preload fragments to registers
    {
        int row = tid >> 1, halfr = tid & 1;
        const uint4* src = (const uint4*)(qsg + (size_t)(b * TT + qbase + row) * 512 + h * 64 + halfr * 32);
        #pragma unroll
        for (int u = 0; u < 4; u++) {
            uint4 v = src[u];
            uint32_t colb = halfr * 64 + u * 16;
            asm volatile("st.shared.v4.b32 [%0], {%1,%2,%3,%4};"
                         :: "r"(Q0 + row * 128 + (colb ^ ((row & 7) << 4))),
                            "r"(v.x), "r"(v.y), "r"(v.z), "r"(v.w) : "memory");
        }
    }
    __syncthreads();

    const int a_roff = lane & 15;
    const int a_cext = (lane & 16) ? 16 : 0;
    const int b_roff = (lane & 7) + ((lane & 16) ? 8 : 0);
    const int b_cext = (lane & 8) ? 16 : 0;
    const int v_cext = (lane & 16) ? 16 : 0;

    uint32_t qf[4][4];
    #pragma unroll
    for (int ks = 0; ks < 4; ks++) {
        int row = wq * 16 + a_roff;
        LDSM4(qf[ks], Q0 + row * 128 + (((ks << 5) + a_cext) ^ ((row & 7) << 4)));
    }

    float acco[8][4];
    #pragma unroll
    for (int t = 0; t < 8; t++)
        #pragma unroll
        for (int u = 0; u < 4; u++) acco[t][u] = 0.0f;
    float m0 = -1e30f, m1 = -1e30f, l0 = 0.0f, l1 = 0.0f;
    const int r0 = lane >> 2;
    const int qlr0 = wq * 16 + r0;
    const int qlr1 = qlr0 + 8;

    for (int jt = 0; jt <= it; jt++) {
        asm volatile("cp.async.wait_group 1;" ::: "memory");   // K(jt) done
        __syncthreads();

        // S = Q @ K^T  (m16 per warp, n64, k64)
        float accs[8][4];
        #pragma unroll
        for (int t = 0; t < 8; t++)
            #pragma unroll
            for (int u = 0; u < 4; u++) accs[t][u] = 0.0f;
        #pragma unroll
        for (int ks = 0; ks < 4; ks++) {
            uint32_t bf[4][4];
            #pragma unroll
            for (int g = 0; g < 4; g++) {
                int row = g * 16 + b_roff;
                LDSM4(bf[g], K0 + row * 128 + (((ks << 5) + b_cext) ^ ((row & 7) << 4)));
            }
            #pragma unroll
            for (int nj = 0; nj < 8; nj++)
                mma16816(accs[nj], qf[ks],
                         bf[nj >> 1][(nj & 1) << 1], bf[nj >> 1][((nj & 1) << 1) + 1]);
        }
        __syncthreads();   // all warps done reading K(jt)
        if (jt < it) { issue_K(jt + 1); issue_V(jt + 1); }

        // softmax (register-resident)
        if (jt == it) {
            #pragma unroll
            for (int t = 0; t < 8; t++) {
                int c0 = t * 8 + (lane & 3) * 2;
                if (c0     > qlr0) accs[t][0] = -1e30f;
                if (c0 + 1 > qlr0) accs[t][1] = -1e30f;
                if (c0     > qlr1) accs[t][2] = -1e30f;
                if (c0 + 1 > qlr1) accs[t][3] = -1e30f;
            }
        }
        float mx0 = -1e30f, mx1 = -1e30f;
        #pragma unroll
        for (int t = 0; t < 8; t++) {
            mx0 = fmaxf(mx0, fmaxf(accs[t][0], accs[t][1]));
            mx1 = fmaxf(mx1, fmaxf(accs[t][2], accs[t][3]));
        }
        mx0 = fmaxf(mx0, __shfl_xor_sync(0xffffffffu, mx0, 1));
        mx0 = fmaxf(mx0, __shfl_xor_sync(0xffffffffu, mx0, 2));
        mx1 = fmaxf(mx1, __shfl_xor_sync(0xffffffffu, mx1, 1));
        mx1 = fmaxf(mx1, __shfl_xor_sync(0xffffffffu, mx1, 2));
        float nm0 = fmaxf(m0, mx0), nm1 = fmaxf(m1, mx1);
        float al0 = __expf(m0 - nm0), al1 = __expf(m1 - nm1);
        float s0 = 0.0f, s1 = 0.0f;
        #pragma unroll
        for (int t = 0; t < 8; t++) {
            accs[t][0] = __expf(accs[t][0] - nm0);
            accs[t][1] = __expf(accs[t][1] - nm0);
            accs[t][2] = __expf(accs[t][2] - nm1);
            accs[t][3] = __expf(accs[t][3] - nm1);
            s0 += accs[t][0] + accs[t][1];
            s1 += accs[t][2] + accs[t][3];
        }
        s0 += __shfl_xor_sync(0xffffffffu, s0, 1);
        s0 += __shfl_xor_sync(0xffffffffu, s0, 2);
        s1 += __shfl_xor_sync(0xffffffffu, s1, 1);
        s1 += __shfl_xor_sync(0xffffffffu, s1, 2);
        l0 = l0 * al0 + s0;
        l1 = l1 * al1 + s1;
        m0 = nm0; m1 = nm1;
        #pragma unroll
        for (int t = 0; t < 8; t++) {
            acco[t][0] *= al0; acco[t][1] *= al0;
            acco[t][2] *= al1; acco[t][3] *= al1;
        }

        if (jt < it) asm volatile("cp.async.wait_group 2;" ::: "memory");   // V(jt) done
        else         asm volatile("cp.async.wait_group 0;" ::: "memory");
        __syncthreads();

        // O += P @ V  (P single fp16, register fragments; V single pass)
        const uint32_t vb = V0 + (uint32_t)(jt & 1) * V_BUF;
        #pragma unroll
        for (int t = 0; t < 4; t++) {
            uint32_t af[4];
            af[0] = pack_h2(__float2half_rn(accs[2*t][0]),   __float2half_rn(accs[2*t][1]));
            af[1] = pack_h2(__float2half_rn(accs[2*t][2]),   __float2half_rn(accs[2*t][3]));
            af[2] = pack_h2(__float2half_rn(accs[2*t+1][0]), __float2half_rn(accs[2*t+1][1]));
            af[3] = pack_h2(__float2half_rn(accs[2*t+1][2]), __float2half_rn(accs[2*t+1][3]));
            uint32_t bh[4][4];
            #pragma unroll
            for (int g = 0; g < 4; g++) {
                int row = t * 16 + (lane & 15);
                LDSM4T(bh[g], vb + row * 128 + (((g << 5) + v_cext) ^ ((row & 7) << 4)));
            }
            #pragma unroll
            for (int nj = 0; nj < 8; nj++)
                mma16816(acco[nj], af, bh[nj >> 1][(nj & 1) << 1], bh[nj >> 1][((nj & 1) << 1) + 1]);
        }
    }

    // epilogue: divide by l, write fp16 o [tok][512]
    const float i0 = 1.0f / l0, i1 = 1.0f / l1;
    const int gr0 = b * TT + qbase + qlr0;
    const int gr1 = b * TT + qbase + qlr1;
    #pragma unroll
    for (int t = 0; t < 8; t++) {
        int e = t * 8 + (lane & 3) * 2;
        *(__half2*)(o_out + (size_t)gr0 * 512 + h * 64 + e) =
            __halves2half2(__float2half_rn(acco[t][0] * i0), __float2half_rn(acco[t][1] * i0));
        *(__half2*)(o_out + (size_t)gr1 * 512 + h * 64 + e) =
            __halves2half2(__float2half_rn(acco[t][2] * i1), __float2half_rn(acco[t][3] * i1));
    }
}

// ---------------- launch ----------------
extern "C" void kernel_launch(void* const* d_in, const int* in_sizes, int n_in,
                              void* d_out, int out_size) {
    const float* x     = (const float*)d_in[0];
    const float* ln1_g = (const float*)d_in[1];
    const float* ln1_b = (const float*)d_in[2];
    const float* Wq    = (const float*)d_in[3];
    const float* Wk    = (const float*)d_in[4];
    const float* Wv    = (const float*)d_in[5];
    const float* Wproj = (const float*)d_in[6];
    const float* bproj = (const float*)d_in[7];
    const float* W1    = (const float*)d_in[8];
    const float* b1    = (const float*)d_in[9];
    const float* W2    = (const float*)d_in[10];
    const float* b2    = (const float*)d_in[11];
    float* out = (float*)d_out;

    float* p_x1;
    __half *p_abf, *p_abf2, *p_bbf, *p_qs, *p_ks, *p_vs;
    cudaGetSymbolAddress((void**)&p_x1,   g_x1);
    cudaGetSymbolAddress((void**)&p_abf,  g_abf);
    cudaGetSymbolAddress((void**)&p_abf2, g_abf2);
    cudaGetSymbolAddress((void**)&p_bbf,  g_bbf);
    cudaGetSymbolAddress((void**)&p_qs,   g_qs);
    cudaGetSymbolAddress((void**)&p_ks,   g_ks);
    cudaGetSymbolAddress((void**)&p_vs,   g_vs);

    cudaFuncSetAttribute(attn_mma, cudaFuncAttributeMaxDynamicSharedMemorySize, ATT_SMEM);
    cudaFuncSetAttribute(mma_gemm, cudaFuncAttributeMaxDynamicSharedMemorySize, GEMM_SMEM);

    // ---- attention sublayer ----
    ln_h_kernel<<<BT, 128>>>(x, ln1_g, ln1_b, p_abf);
    repack_qkvTh_kernel<<<(1536 * DDIM + 255) / 256, 256>>>(Wq, Wk, Wv, p_bbf);
    // mode 2: q->Ko(g_qs), k->Cs(g_ks), v->Vo(g_vs)
    mma_gemm<<<dim3(1536 / 128, BT / 128), 256, GEMM_SMEM>>>(
        p_abf, p_bbf, nullptr, nullptr, nullptr, p_ks, p_qs, p_vs, 1536, 512, 0, 2);
    attn_mma<<<dim3(TT / 64, HH, BB), 128, ATT_SMEM>>>(p_qs, p_ks, p_vs, p_abf);

    transposeh_kernel<<<dim3(DDIM / 32, DDIM / 32), dim3(32, 8)>>>(Wproj, p_bbf, DDIM, DDIM);
    mma_gemm<<<dim3(DDIM / 128, BT / 128), 256, GEMM_SMEM>>>(
        p_abf, p_bbf, bproj, x, p_x1, nullptr, nullptr, nullptr, DDIM, 512, 0, 0);

    // ---- FFN sublayer ----
    ln_h_kernel<<<BT, 128>>>(p_x1, ln1_g, ln1_b, p_abf);
    transposeh_kernel<<<dim3(FFD / 32, DDIM / 32), dim3(32, 8)>>>(W1, p_bbf, DDIM, FFD);
    mma_gemm<<<dim3(FFD / 128, BT / 128), 256, GEMM_SMEM>>>(
        p_abf, p_bbf, b1, nullptr, nullptr, p_abf2, nullptr, nullptr, FFD, 512, 1, 1);

    transposeh_kernel<<<dim3(DDIM / 32, FFD / 32), dim3(32, 8)>>>(W2, p_bbf, FFD, DDIM);
    mma_gemm<<<dim3(DDIM / 128, BT / 128), 256, GEMM_SMEM>>>(
        p_abf2, p_bbf, b2, p_x1, out, nullptr, nullptr, nullptr, DDIM, 2048, 0, 0);
}